// round 1
// baseline (speedup 1.0000x reference)
#include <cuda_runtime.h>

// CoPEModel GCN on GB300: CSR-build (per launch) + pull-mode SpMM + fused GEMM/BN-stats.
// Inputs (metadata order): x, src, dst, W1, b1, g1, be1, W2, b2, g2, be2, Wc, bc
// Output: [1,2] float32.

#define NMAX 100000
#define EMAX 1600000

// ---------------- device scratch (static globals; no allocation) ----------------
__device__ __align__(16) int   g_deg_out[NMAX];
__device__ __align__(16) int   g_deg_in[NMAX];
__device__ __align__(16) float g_rs_out[NMAX];
__device__ __align__(16) float g_rs_in[NMAX];
__device__ __align__(16) int   g_row_ptr[NMAX + 1];
__device__ __align__(16) int   g_fill[NMAX];
__device__ __align__(16) int   g_col[EMAX];
__device__ __align__(16) float g_m[(size_t)NMAX * 64];   // aggregated messages
__device__ __align__(16) float g_h[(size_t)NMAX * 64];   // post-GEMM
__device__ __align__(16) float g_a[(size_t)NMAX * 64];   // post-BN/ReLU
__device__ __align__(16) float g_sum[64];
__device__ __align__(16) float g_sumsq[64];
__device__ __align__(16) float g_mu[64];
__device__ __align__(16) float g_istd[64];
__device__ __align__(16) float g_colsum[64];

#define EPSV 1e-5f

// ---------------- graph preprocessing ----------------

__global__ void k_zero_graph(int n) {
    int i = blockIdx.x * blockDim.x + threadIdx.x;
    if (i < n) { g_deg_out[i] = 0; g_deg_in[i] = 0; g_fill[i] = 0; }
}

__global__ void k_deg(const int* __restrict__ src, const int* __restrict__ dst, int e) {
    int i = blockIdx.x * blockDim.x + threadIdx.x;
    if (i < e) {
        atomicAdd(&g_deg_out[src[i]], 1);
        atomicAdd(&g_deg_in[dst[i]], 1);
    }
}

__global__ void k_rsqrt_deg(int n) {
    int i = blockIdx.x * blockDim.x + threadIdx.x;
    if (i < n) {
        g_rs_out[i] = rsqrtf((float)max(g_deg_out[i], 1));
        g_rs_in[i]  = rsqrtf((float)max(g_deg_in[i], 1));
    }
}

// Single-block exclusive scan of g_deg_in -> g_row_ptr (n up to 100352 with 1024 thr)
__global__ void k_scan(int n) {
    __shared__ int sh[1024];
    int t = threadIdx.x;
    int chunk = (n + 1023) >> 10;
    int beg = t * chunk;
    int end = min(beg + chunk, n);
    int s = 0;
    for (int i = beg; i < end; i++) s += g_deg_in[i];
    sh[t] = s;
    __syncthreads();
    for (int off = 1; off < 1024; off <<= 1) {
        int v = (t >= off) ? sh[t - off] : 0;
        __syncthreads();
        sh[t] += v;
        __syncthreads();
    }
    int base = (t > 0) ? sh[t - 1] : 0;
    for (int i = beg; i < end; i++) { g_row_ptr[i] = base; base += g_deg_in[i]; }
    if (end == n) g_row_ptr[n] = base;  // several threads may write identical total
}

__global__ void k_scatter(const int* __restrict__ src, const int* __restrict__ dst, int e) {
    int i = blockIdx.x * blockDim.x + threadIdx.x;
    if (i < e) {
        int d = dst[i];
        int p = g_row_ptr[d] + atomicAdd(&g_fill[d], 1);
        g_col[p] = src[i];
    }
}

// ---------------- pull-mode SpMM ----------------
// m[v] = rs_in[v] * sum_{u in N_in(v)} rs_out[u] * in[u]
// One warp per node; lane owns 2 features (float2). Edge indices/scales are
// prefetched lane-parallel (MLP up to 32), broadcast via shfl.
__global__ void k_spmm(const float* __restrict__ xin, int use_x, int n) {
    const float* __restrict__ in = use_x ? xin : g_a;
    int warp = (blockIdx.x * blockDim.x + threadIdx.x) >> 5;
    int lane = threadIdx.x & 31;
    if (warp >= n) return;
    int beg = g_row_ptr[warp], end = g_row_ptr[warp + 1];
    float2 acc = make_float2(0.f, 0.f);
    for (int base = beg; base < end; base += 32) {
        int idx = base + lane;
        int u = (idx < end) ? g_col[idx] : 0;
        float sc = (idx < end) ? g_rs_out[u] : 0.f;
        int cnt = min(32, end - base);
        #pragma unroll 4
        for (int j = 0; j < cnt; j++) {
            int   uu = __shfl_sync(0xffffffffu, u, j);
            float ss = __shfl_sync(0xffffffffu, sc, j);
            float2 v = *(const float2*)(in + (size_t)uu * 64 + lane * 2);
            acc.x = fmaf(ss, v.x, acc.x);
            acc.y = fmaf(ss, v.y, acc.y);
        }
    }
    float ri = g_rs_in[warp];
    float2 o = make_float2(acc.x * ri, acc.y * ri);
    *(float2*)(g_m + (size_t)warp * 64 + lane * 2) = o;
}

// ---------------- GEMM (g_m @ W + b -> g_h) with fused BN statistics ----------------
// Block: 256 threads covering 32 rows. Thread (rslot=t>>4, jg=t&15) computes
// 4 output cols (float4) for rows rslot and rslot+16. W staged in shared.
__global__ void k_zero_stats() {
    int t = threadIdx.x;
    if (t < 64) { g_sum[t] = 0.f; g_sumsq[t] = 0.f; g_colsum[t] = 0.f; }
}

__global__ void k_gemm(const float* __restrict__ W, const float* __restrict__ bias, int n) {
    __shared__ float4 Ws[1024];        // 64 x 16 float4 = 16 KB
    __shared__ float  s_sum[16][64];
    __shared__ float  s_sq[16][64];
    int t = threadIdx.x;
    for (int i = t; i < 1024; i += 256) Ws[i] = ((const float4*)W)[i];
    __syncthreads();

    int jg = t & 15, rslot = t >> 4;
    float4 b4 = ((const float4*)bias)[jg];
    float ls0 = 0, ls1 = 0, ls2 = 0, ls3 = 0;
    float lq0 = 0, lq1 = 0, lq2 = 0, lq3 = 0;

    #pragma unroll
    for (int rr = 0; rr < 2; rr++) {
        int row = blockIdx.x * 32 + rslot + rr * 16;
        if (row < n) {
            const float4* mrow = (const float4*)(g_m + (size_t)row * 64);
            float4 acc = b4;
            #pragma unroll
            for (int k4 = 0; k4 < 16; k4++) {
                float4 m4 = __ldg(&mrow[k4]);
                float4 w;
                w = Ws[(k4 * 4 + 0) * 16 + jg];
                acc.x = fmaf(m4.x, w.x, acc.x); acc.y = fmaf(m4.x, w.y, acc.y);
                acc.z = fmaf(m4.x, w.z, acc.z); acc.w = fmaf(m4.x, w.w, acc.w);
                w = Ws[(k4 * 4 + 1) * 16 + jg];
                acc.x = fmaf(m4.y, w.x, acc.x); acc.y = fmaf(m4.y, w.y, acc.y);
                acc.z = fmaf(m4.y, w.z, acc.z); acc.w = fmaf(m4.y, w.w, acc.w);
                w = Ws[(k4 * 4 + 2) * 16 + jg];
                acc.x = fmaf(m4.z, w.x, acc.x); acc.y = fmaf(m4.z, w.y, acc.y);
                acc.z = fmaf(m4.z, w.z, acc.z); acc.w = fmaf(m4.z, w.w, acc.w);
                w = Ws[(k4 * 4 + 3) * 16 + jg];
                acc.x = fmaf(m4.w, w.x, acc.x); acc.y = fmaf(m4.w, w.y, acc.y);
                acc.z = fmaf(m4.w, w.z, acc.z); acc.w = fmaf(m4.w, w.w, acc.w);
            }
            ((float4*)(g_h + (size_t)row * 64))[jg] = acc;
            ls0 += acc.x; ls1 += acc.y; ls2 += acc.z; ls3 += acc.w;
            lq0 += acc.x * acc.x; lq1 += acc.y * acc.y;
            lq2 += acc.z * acc.z; lq3 += acc.w * acc.w;
        }
    }
    s_sum[rslot][jg * 4 + 0] = ls0; s_sum[rslot][jg * 4 + 1] = ls1;
    s_sum[rslot][jg * 4 + 2] = ls2; s_sum[rslot][jg * 4 + 3] = ls3;
    s_sq[rslot][jg * 4 + 0] = lq0;  s_sq[rslot][jg * 4 + 1] = lq1;
    s_sq[rslot][jg * 4 + 2] = lq2;  s_sq[rslot][jg * 4 + 3] = lq3;
    __syncthreads();
    if (t < 64) {
        float a = 0, q = 0;
        #pragma unroll
        for (int r = 0; r < 16; r++) { a += s_sum[r][t]; q += s_sq[r][t]; }
        atomicAdd(&g_sum[t], a);
        atomicAdd(&g_sumsq[t], q);
    }
}

__global__ void k_bn_finalize(int n) {
    int j = threadIdx.x;
    if (j < 64) {
        float inv_n = 1.f / (float)n;
        float mu = g_sum[j] * inv_n;
        float var = g_sumsq[j] * inv_n - mu * mu;
        g_mu[j] = mu;
        g_istd[j] = rsqrtf(var + EPSV);
    }
}

// BN + ReLU elementwise; conv-2 pass also accumulates per-channel column sums
// for the graph readout. Thread t: col group cg=t&15 (4 cols), row lane rl=t>>4.
__global__ void k_bnrelu(const float* __restrict__ gma, const float* __restrict__ bet,
                         int n, int do_colsum) {
    int cg = threadIdx.x & 15;
    int rl = threadIdx.x >> 4;
    float4 gm4 = ((const float4*)gma)[cg];
    float4 be4 = ((const float4*)bet)[cg];
    float4 mu4 = ((const float4*)g_mu)[cg];
    float4 is4 = ((const float4*)g_istd)[cg];
    float4 sc, sf;
    sc.x = is4.x * gm4.x; sf.x = be4.x - mu4.x * sc.x;
    sc.y = is4.y * gm4.y; sf.y = be4.y - mu4.y * sc.y;
    sc.z = is4.z * gm4.z; sf.z = be4.z - mu4.z * sc.z;
    sc.w = is4.w * gm4.w; sf.w = be4.w - mu4.w * sc.w;

    float4 acc = make_float4(0.f, 0.f, 0.f, 0.f);
    for (int row = blockIdx.x * 16 + rl; row < n; row += gridDim.x * 16) {
        float4 h = ((const float4*)(g_h + (size_t)row * 64))[cg];
        float4 y;
        y.x = fmaxf(fmaf(h.x, sc.x, sf.x), 0.f);
        y.y = fmaxf(fmaf(h.y, sc.y, sf.y), 0.f);
        y.z = fmaxf(fmaf(h.z, sc.z, sf.z), 0.f);
        y.w = fmaxf(fmaf(h.w, sc.w, sf.w), 0.f);
        ((float4*)(g_a + (size_t)row * 64))[cg] = y;
        if (do_colsum) { acc.x += y.x; acc.y += y.y; acc.z += y.z; acc.w += y.w; }
    }
    if (do_colsum) {
        __shared__ float s[16][64];
        s[rl][cg * 4 + 0] = acc.x; s[rl][cg * 4 + 1] = acc.y;
        s[rl][cg * 4 + 2] = acc.z; s[rl][cg * 4 + 3] = acc.w;
        __syncthreads();
        if (threadIdx.x < 64) {
            float tsum = 0;
            #pragma unroll
            for (int r = 0; r < 16; r++) tsum += s[r][threadIdx.x];
            atomicAdd(&g_colsum[threadIdx.x], tsum);
        }
    }
}

// Final readout: out[j] = bc[j] + sum_k (colsum[k]/n) * Wc[k][j]
__global__ void k_final(const float* __restrict__ Wc, const float* __restrict__ bc,
                        float* __restrict__ out, int n) {
    __shared__ float s0[64], s1[64];
    int t = threadIdx.x;
    float v = g_colsum[t] / (float)n;
    s0[t] = v * Wc[t * 2 + 0];
    s1[t] = v * Wc[t * 2 + 1];
    __syncthreads();
    if (t == 0) {
        float a = 0.f, b = 0.f;
        for (int k = 0; k < 64; k++) { a += s0[k]; b += s1[k]; }
        out[0] = a + bc[0];
        out[1] = b + bc[1];
    }
}

// ---------------- launch ----------------
extern "C" void kernel_launch(void* const* d_in, const int* in_sizes, int n_in,
                              void* d_out, int out_size) {
    const float* x   = (const float*)d_in[0];
    const int*   src = (const int*)d_in[1];
    const int*   dst = (const int*)d_in[2];
    const float* W1  = (const float*)d_in[3];
    const float* b1  = (const float*)d_in[4];
    const float* g1  = (const float*)d_in[5];
    const float* be1 = (const float*)d_in[6];
    const float* W2  = (const float*)d_in[7];
    const float* b2  = (const float*)d_in[8];
    const float* g2  = (const float*)d_in[9];
    const float* be2 = (const float*)d_in[10];
    const float* Wc  = (const float*)d_in[11];
    const float* bc  = (const float*)d_in[12];
    float* out = (float*)d_out;

    int n = in_sizes[0] / 64;
    int e = in_sizes[1];

    int nb = (n + 255) / 256;
    int eb = (e + 255) / 256;
    int spmm_blocks = (n + 7) / 8;       // 8 warps per 256-thread block
    int gemm_blocks = (n + 31) / 32;

    // graph preprocessing (CSR by dst) — reused by both convs
    k_zero_graph<<<nb, 256>>>(n);
    k_deg<<<eb, 256>>>(src, dst, e);
    k_rsqrt_deg<<<nb, 256>>>(n);
    k_scan<<<1, 1024>>>(n);
    k_scatter<<<eb, 256>>>(src, dst, e);

    // conv 1
    k_spmm<<<spmm_blocks, 256>>>(x, 1, n);
    k_zero_stats<<<1, 64>>>();
    k_gemm<<<gemm_blocks, 256>>>(W1, b1, n);
    k_bn_finalize<<<1, 64>>>(n);
    k_bnrelu<<<512, 256>>>(g1, be1, n, 0);

    // conv 2
    k_spmm<<<spmm_blocks, 256>>>(nullptr, 0, n);
    k_zero_stats<<<1, 64>>>();
    k_gemm<<<gemm_blocks, 256>>>(W2, b2, n);
    k_bn_finalize<<<1, 64>>>(n);
    k_bnrelu<<<512, 256>>>(g2, be2, n, 1);

    // readout + classifier
    k_final<<<1, 64>>>(Wc, bc, out, n);
    (void)n_in; (void)out_size;
}

// round 4
// speedup vs baseline: 1.2309x; 1.2309x over previous
#include <cuda_runtime.h>

// CoPEModel GCN on GB300.
// CSR-build (full-chip 3-phase scan) + pull-mode SpMM (packed edge records,
// conv-1 BN/ReLU fused into SpMM-2) + GEMM with fused BN statistics.
// Inputs (metadata order): x, src, dst, W1, b1, g1, be1, W2, b2, g2, be2, Wc, bc
// Output: [1,2] float32.

#define NMAX 100000
#define EMAX 1600000

#define SCAN_BLOCKS 128
#define SCAN_TPB    256
#define SCAN_T      (SCAN_BLOCKS * SCAN_TPB)   // 32768 scan threads
#define SCAN_CHUNK  4                          // ceil(100000/32768)

#define EPSV 1e-5f

// ---------------- device scratch (static globals; no allocation) ----------------
__device__ __align__(16) int   g_deg_out[NMAX];
__device__ __align__(16) int   g_deg_in[NMAX];
__device__ __align__(16) float g_rs_out[NMAX];
__device__ __align__(16) float g_rs_in[NMAX];
__device__ __align__(16) int   g_row_ptr[NMAX + 1];
__device__ __align__(16) int   g_fill[NMAX];
__device__ __align__(16) int2  g_edge[EMAX];             // {src, bits(rs_out[src])}
__device__ __align__(16) int   g_tsum[SCAN_T];
__device__ __align__(16) int   g_tpre[SCAN_T];
__device__ __align__(16) float g_m[(size_t)NMAX * 64];   // aggregated messages
__device__ __align__(16) float g_h[(size_t)NMAX * 64];   // post-GEMM (reused both convs)
__device__ __align__(16) float g_sum[64];
__device__ __align__(16) float g_sumsq[64];
__device__ __align__(16) float g_mu[64];
__device__ __align__(16) float g_istd[64];
__device__ __align__(16) float g_colsum[64];

// ---------------- graph preprocessing ----------------

__global__ void k_zero_graph(int n) {
    int i = blockIdx.x * blockDim.x + threadIdx.x;
    if (i < n) { g_deg_out[i] = 0; g_deg_in[i] = 0; g_fill[i] = 0; }
    if (i < 64) { g_sum[i] = 0.f; g_sumsq[i] = 0.f; g_colsum[i] = 0.f; }
}

__global__ void k_deg(const int* __restrict__ src, const int* __restrict__ dst, int e) {
    int i = blockIdx.x * blockDim.x + threadIdx.x;
    if (i < e) {
        atomicAdd(&g_deg_out[src[i]], 1);
        atomicAdd(&g_deg_in[dst[i]], 1);
    }
}

// Phase 1: per-scan-thread partial sums of deg_in; also rsqrt of both degrees.
__global__ void k_scan_p1(int n) {
    int g = blockIdx.x * blockDim.x + threadIdx.x;
    int beg = g * SCAN_CHUNK;
    int end = min(beg + SCAN_CHUNK, n);
    int s = 0;
    for (int i = beg; i < end; i++) {
        int di = g_deg_in[i];
        s += di;
        g_rs_in[i]  = rsqrtf((float)max(di, 1));
        g_rs_out[i] = rsqrtf((float)max(g_deg_out[i], 1));
    }
    g_tsum[g] = s;
}

// Phase 2: one 1024-thread block scans the 32768 partials (32 per thread).
__global__ void k_scan_p2() {
    __shared__ int sh[1024];
    int t = threadIdx.x;
    int s = 0;
    #pragma unroll 8
    for (int j = 0; j < 32; j++) s += g_tsum[t * 32 + j];
    sh[t] = s;
    __syncthreads();
    for (int off = 1; off < 1024; off <<= 1) {
        int v = (t >= off) ? sh[t - off] : 0;
        __syncthreads();
        sh[t] += v;
        __syncthreads();
    }
    int base = (t > 0) ? sh[t - 1] : 0;
    #pragma unroll 8
    for (int j = 0; j < 32; j++) {
        int idx = t * 32 + j;
        g_tpre[idx] = base;
        base += g_tsum[idx];
    }
}

// Phase 3: write row_ptr from per-thread prefixes.
__global__ void k_scan_p3(int n) {
    int g = blockIdx.x * blockDim.x + threadIdx.x;
    int beg = g * SCAN_CHUNK;
    int end = min(beg + SCAN_CHUNK, n);
    int base = g_tpre[g];
    for (int i = beg; i < end; i++) { g_row_ptr[i] = base; base += g_deg_in[i]; }
    if (end == n && beg < n) g_row_ptr[n] = base;
}

// Scatter edges into CSR slots; pack source index + its out-degree scale.
__global__ void k_scatter(const int* __restrict__ src, const int* __restrict__ dst, int e) {
    int i = blockIdx.x * blockDim.x + threadIdx.x;
    if (i < e) {
        int d = dst[i];
        int s = src[i];
        int p = g_row_ptr[d] + atomicAdd(&g_fill[d], 1);
        g_edge[p] = make_int2(s, __float_as_int(g_rs_out[s]));
    }
}

// ---------------- pull-mode SpMM ----------------
// m[v] = rs_in[v] * sum_{u in N_in(v)} rs_out[u] * f(in[u])
// USE_X=1: f = identity, in = x (conv 1).
// USE_X=0: f = relu(bn(.)) applied on the fly to g_h (conv 2; fuses conv-1 epilogue).
// One warp per node; lane owns 2 feature channels (float2). Edge records
// loaded lane-parallel, broadcast via shfl; inner loop unrolled x2 for MLP.
template <int USE_X>
__global__ void k_spmm(const float* __restrict__ xin,
                       const float* __restrict__ gma, const float* __restrict__ bet,
                       int n) {
    const float* __restrict__ in = USE_X ? xin : g_h;
    int warp = (blockIdx.x * blockDim.x + threadIdx.x) >> 5;
    int lane = threadIdx.x & 31;
    if (warp >= n) return;

    float scx = 0.f, scy = 0.f, sfx = 0.f, sfy = 0.f;
    if (!USE_X) {
        int c0 = lane * 2, c1 = c0 + 1;
        scx = g_istd[c0] * gma[c0]; sfx = bet[c0] - g_mu[c0] * scx;
        scy = g_istd[c1] * gma[c1]; sfy = bet[c1] - g_mu[c1] * scy;
    }

    int beg = g_row_ptr[warp], end = g_row_ptr[warp + 1];
    float2 acc = make_float2(0.f, 0.f);

    for (int base = beg; base < end; base += 32) {
        int idx = base + lane;
        int2 ep = (idx < end) ? g_edge[idx] : make_int2(0, 0);
        int cnt = min(32, end - base);
        int j = 0;
        for (; j + 2 <= cnt; j += 2) {
            int   u0 = __shfl_sync(0xffffffffu, ep.x, j);
            float s0 = __int_as_float(__shfl_sync(0xffffffffu, ep.y, j));
            int   u1 = __shfl_sync(0xffffffffu, ep.x, j + 1);
            float s1 = __int_as_float(__shfl_sync(0xffffffffu, ep.y, j + 1));
            float2 v0 = *(const float2*)(in + (size_t)u0 * 64 + lane * 2);
            float2 v1 = *(const float2*)(in + (size_t)u1 * 64 + lane * 2);
            if (!USE_X) {
                v0.x = fmaxf(fmaf(v0.x, scx, sfx), 0.f);
                v0.y = fmaxf(fmaf(v0.y, scy, sfy), 0.f);
                v1.x = fmaxf(fmaf(v1.x, scx, sfx), 0.f);
                v1.y = fmaxf(fmaf(v1.y, scy, sfy), 0.f);
            }
            acc.x = fmaf(s0, v0.x, acc.x);
            acc.y = fmaf(s0, v0.y, acc.y);
            acc.x = fmaf(s1, v1.x, acc.x);
            acc.y = fmaf(s1, v1.y, acc.y);
        }
        if (j < cnt) {
            int   u0 = __shfl_sync(0xffffffffu, ep.x, j);
            float s0 = __int_as_float(__shfl_sync(0xffffffffu, ep.y, j));
            float2 v0 = *(const float2*)(in + (size_t)u0 * 64 + lane * 2);
            if (!USE_X) {
                v0.x = fmaxf(fmaf(v0.x, scx, sfx), 0.f);
                v0.y = fmaxf(fmaf(v0.y, scy, sfy), 0.f);
            }
            acc.x = fmaf(s0, v0.x, acc.x);
            acc.y = fmaf(s0, v0.y, acc.y);
        }
    }
    float ri = g_rs_in[warp];
    *(float2*)(g_m + (size_t)warp * 64 + lane * 2) = make_float2(acc.x * ri, acc.y * ri);
}

// ---------------- GEMM (g_m @ W + b -> g_h) with fused BN statistics ----------------
__global__ void k_gemm(const float* __restrict__ W, const float* __restrict__ bias, int n) {
    __shared__ float4 Ws[1024];        // 64 x 16 float4 = 16 KB
    __shared__ float  s_sum[16][64];
    __shared__ float  s_sq[16][64];
    int t = threadIdx.x;
    for (int i = t; i < 1024; i += 256) Ws[i] = ((const float4*)W)[i];
    __syncthreads();

    int jg = t & 15, rslot = t >> 4;
    float4 b4 = ((const float4*)bias)[jg];
    float ls0 = 0, ls1 = 0, ls2 = 0, ls3 = 0;
    float lq0 = 0, lq1 = 0, lq2 = 0, lq3 = 0;

    #pragma unroll
    for (int rr = 0; rr < 2; rr++) {
        int row = blockIdx.x * 32 + rslot + rr * 16;
        if (row < n) {
            const float4* mrow = (const float4*)(g_m + (size_t)row * 64);
            float4 acc = b4;
            #pragma unroll
            for (int k4 = 0; k4 < 16; k4++) {
                float4 m4 = __ldg(&mrow[k4]);
                float4 w;
                w = Ws[(k4 * 4 + 0) * 16 + jg];
                acc.x = fmaf(m4.x, w.x, acc.x); acc.y = fmaf(m4.x, w.y, acc.y);
                acc.z = fmaf(m4.x, w.z, acc.z); acc.w = fmaf(m4.x, w.w, acc.w);
                w = Ws[(k4 * 4 + 1) * 16 + jg];
                acc.x = fmaf(m4.y, w.x, acc.x); acc.y = fmaf(m4.y, w.y, acc.y);
                acc.z = fmaf(m4.y, w.z, acc.z); acc.w = fmaf(m4.y, w.w, acc.w);
                w = Ws[(k4 * 4 + 2) * 16 + jg];
                acc.x = fmaf(m4.z, w.x, acc.x); acc.y = fmaf(m4.z, w.y, acc.y);
                acc.z = fmaf(m4.z, w.z, acc.z); acc.w = fmaf(m4.z, w.w, acc.w);
                w = Ws[(k4 * 4 + 3) * 16 + jg];
                acc.x = fmaf(m4.w, w.x, acc.x); acc.y = fmaf(m4.w, w.y, acc.y);
                acc.z = fmaf(m4.w, w.z, acc.z); acc.w = fmaf(m4.w, w.w, acc.w);
            }
            ((float4*)(g_h + (size_t)row * 64))[jg] = acc;
            ls0 += acc.x; ls1 += acc.y; ls2 += acc.z; ls3 += acc.w;
            lq0 += acc.x * acc.x; lq1 += acc.y * acc.y;
            lq2 += acc.z * acc.z; lq3 += acc.w * acc.w;
        }
    }
    s_sum[rslot][jg * 4 + 0] = ls0; s_sum[rslot][jg * 4 + 1] = ls1;
    s_sum[rslot][jg * 4 + 2] = ls2; s_sum[rslot][jg * 4 + 3] = ls3;
    s_sq[rslot][jg * 4 + 0] = lq0;  s_sq[rslot][jg * 4 + 1] = lq1;
    s_sq[rslot][jg * 4 + 2] = lq2;  s_sq[rslot][jg * 4 + 3] = lq3;
    __syncthreads();
    if (t < 64) {
        float a = 0, q = 0;
        #pragma unroll
        for (int r = 0; r < 16; r++) { a += s_sum[r][t]; q += s_sq[r][t]; }
        atomicAdd(&g_sum[t], a);
        atomicAdd(&g_sumsq[t], q);
    }
}

// Finalize BN stats, then re-zero accumulators for the next conv.
__global__ void k_bn_finalize(int n) {
    int j = threadIdx.x;
    if (j < 64) {
        float inv_n = 1.f / (float)n;
        float mu = g_sum[j] * inv_n;
        float var = g_sumsq[j] * inv_n - mu * mu;
        g_mu[j] = mu;
        g_istd[j] = rsqrtf(var + EPSV);
        g_sum[j] = 0.f;
        g_sumsq[j] = 0.f;
    }
}

// Conv-2 readout: per-channel column sums of relu(bn(g_h)) — no store.
__global__ void k_colsum(const float* __restrict__ gma, const float* __restrict__ bet, int n) {
    int cg = threadIdx.x & 15;
    int rl = threadIdx.x >> 4;
    float4 gm4 = ((const float4*)gma)[cg];
    float4 be4 = ((const float4*)bet)[cg];
    float4 mu4 = ((const float4*)g_mu)[cg];
    float4 is4 = ((const float4*)g_istd)[cg];
    float4 sc, sf;
    sc.x = is4.x * gm4.x; sf.x = be4.x - mu4.x * sc.x;
    sc.y = is4.y * gm4.y; sf.y = be4.y - mu4.y * sc.y;
    sc.z = is4.z * gm4.z; sf.z = be4.z - mu4.z * sc.z;
    sc.w = is4.w * gm4.w; sf.w = be4.w - mu4.w * sc.w;

    float4 acc = make_float4(0.f, 0.f, 0.f, 0.f);
    for (int row = blockIdx.x * 16 + rl; row < n; row += gridDim.x * 16) {
        float4 h = ((const float4*)(g_h + (size_t)row * 64))[cg];
        acc.x += fmaxf(fmaf(h.x, sc.x, sf.x), 0.f);
        acc.y += fmaxf(fmaf(h.y, sc.y, sf.y), 0.f);
        acc.z += fmaxf(fmaf(h.z, sc.z, sf.z), 0.f);
        acc.w += fmaxf(fmaf(h.w, sc.w, sf.w), 0.f);
    }
    __shared__ float s[16][64];
    s[rl][cg * 4 + 0] = acc.x; s[rl][cg * 4 + 1] = acc.y;
    s[rl][cg * 4 + 2] = acc.z; s[rl][cg * 4 + 3] = acc.w;
    __syncthreads();
    if (threadIdx.x < 64) {
        float tsum = 0;
        #pragma unroll
        for (int r = 0; r < 16; r++) tsum += s[r][threadIdx.x];
        atomicAdd(&g_colsum[threadIdx.x], tsum);
    }
}

// Final readout: out[j] = bc[j] + sum_k (colsum[k]/n) * Wc[k][j]
__global__ void k_final(const float* __restrict__ Wc, const float* __restrict__ bc,
                        float* __restrict__ out, int n) {
    __shared__ float s0[64], s1[64];
    int t = threadIdx.x;
    float v = g_colsum[t] / (float)n;
    s0[t] = v * Wc[t * 2 + 0];
    s1[t] = v * Wc[t * 2 + 1];
    __syncthreads();
    if (t == 0) {
        float a = 0.f, b = 0.f;
        for (int k = 0; k < 64; k++) { a += s0[k]; b += s1[k]; }
        out[0] = a + bc[0];
        out[1] = b + bc[1];
    }
}

// ---------------- launch ----------------
extern "C" void kernel_launch(void* const* d_in, const int* in_sizes, int n_in,
                              void* d_out, int out_size) {
    const float* x   = (const float*)d_in[0];
    const int*   src = (const int*)d_in[1];
    const int*   dst = (const int*)d_in[2];
    const float* W1  = (const float*)d_in[3];
    const float* b1  = (const float*)d_in[4];
    const float* g1  = (const float*)d_in[5];
    const float* be1 = (const float*)d_in[6];
    const float* W2  = (const float*)d_in[7];
    const float* b2  = (const float*)d_in[8];
    const float* g2  = (const float*)d_in[9];
    const float* be2 = (const float*)d_in[10];
    const float* Wc  = (const float*)d_in[11];
    const float* bc  = (const float*)d_in[12];
    float* out = (float*)d_out;

    int n = in_sizes[0] / 64;
    int e = in_sizes[1];

    int nb = (n + 255) / 256;
    int eb = (e + 255) / 256;
    int spmm_blocks = (n + 7) / 8;       // 8 warps per 256-thread block
    int gemm_blocks = (n + 31) / 32;

    // graph preprocessing (CSR by dst) — reused by both convs
    k_zero_graph<<<nb, 256>>>(n);
    k_deg<<<eb, 256>>>(src, dst, e);
    k_scan_p1<<<SCAN_BLOCKS, SCAN_TPB>>>(n);
    k_scan_p2<<<1, 1024>>>();
    k_scan_p3<<<SCAN_BLOCKS, SCAN_TPB>>>(n);
    k_scatter<<<eb, 256>>>(src, dst, e);

    // conv 1
    k_spmm<1><<<spmm_blocks, 256>>>(x, nullptr, nullptr, n);
    k_gemm<<<gemm_blocks, 256>>>(W1, b1, n);
    k_bn_finalize<<<1, 64>>>(n);

    // conv 2 (BN+ReLU of conv-1 fused into this SpMM)
    k_spmm<0><<<spmm_blocks, 256>>>(nullptr, g1, be1, n);
    k_gemm<<<gemm_blocks, 256>>>(W2, b2, n);
    k_bn_finalize<<<1, 64>>>(n);

    // readout + classifier
    k_colsum<<<512, 256>>>(g2, be2, n);
    k_final<<<1, 64>>>(Wc, bc, out, n);
    (void)n_in; (void)out_size;
}

// round 5
// speedup vs baseline: 1.5073x; 1.2246x over previous
#include <cuda_runtime.h>

// CoPEModel GCN on GB300.
// CSR-build (3-phase scan, phase-2 = 128 elems) + pull-mode SpMM (uniform edge
// loads, conv-1 BN/ReLU fused into SpMM-2) + f32x2 GEMM with fused BN stats.
// Inputs (metadata order): x, src, dst, W1, b1, g1, be1, W2, b2, g2, be2, Wc, bc
// Output: [1,2] float32.

#define NMAX 100000
#define EMAX 1600000

#define SCAN_BLOCKS 128
#define SCAN_TPB    256
#define SCAN_T      (SCAN_BLOCKS * SCAN_TPB)   // 32768 scan threads
#define SCAN_CHUNK  4                          // ceil(100000/32768)

#define EPSV 1e-5f

typedef unsigned long long ull;

// ---------------- device scratch (static globals; no allocation) ----------------
__device__ __align__(16) int   g_deg_out[NMAX];
__device__ __align__(16) int   g_deg_in[NMAX];
__device__ __align__(16) float g_rs_out[NMAX];
__device__ __align__(16) float g_rs_in[NMAX];
__device__ __align__(16) int   g_row_ptr[NMAX + 1];
__device__ __align__(16) int   g_fill[NMAX];
__device__ __align__(16) int2  g_edge[EMAX];             // {src, bits(rs_out[src])}
__device__ __align__(16) int   g_tpre[SCAN_T];           // within-block exclusive prefix
__device__ __align__(16) int   g_bsum[SCAN_BLOCKS];
__device__ __align__(16) int   g_bpre[SCAN_BLOCKS];
__device__ __align__(16) float g_m[(size_t)NMAX * 64];   // aggregated messages
__device__ __align__(16) float g_h[(size_t)NMAX * 64];   // post-GEMM (reused both convs)
__device__ __align__(16) float g_s1[64];   // conv-1 BN sum
__device__ __align__(16) float g_q1[64];   // conv-1 BN sumsq
__device__ __align__(16) float g_s2[64];   // conv-2 BN sum
__device__ __align__(16) float g_q2[64];   // conv-2 BN sumsq
__device__ __align__(16) float g_colsum[64];

// ---------------- f32x2 helpers ----------------
__device__ __forceinline__ ull f2pack(float a, float b) {
    ull r; asm("mov.b64 %0, {%1, %2};" : "=l"(r) : "f"(a), "f"(b)); return r;
}
__device__ __forceinline__ void f2unpack(ull v, float& a, float& b) {
    asm("mov.b64 {%0, %1}, %2;" : "=f"(a), "=f"(b) : "l"(v));
}
__device__ __forceinline__ ull f2fma(ull a, ull b, ull c) {
    ull d; asm("fma.rn.f32x2 %0, %1, %2, %3;" : "=l"(d) : "l"(a), "l"(b), "l"(c)); return d;
}

// ---------------- graph preprocessing ----------------

__global__ void k_zero_graph(int n) {
    int i = blockIdx.x * blockDim.x + threadIdx.x;
    if (i < n) { g_deg_out[i] = 0; g_deg_in[i] = 0; g_fill[i] = 0; }
    if (i < 64) {
        g_s1[i] = 0.f; g_q1[i] = 0.f;
        g_s2[i] = 0.f; g_q2[i] = 0.f;
        g_colsum[i] = 0.f;
    }
}

__global__ void k_deg(const int* __restrict__ src, const int* __restrict__ dst, int e) {
    int i = blockIdx.x * blockDim.x + threadIdx.x;
    if (i < e) {
        atomicAdd(&g_deg_out[src[i]], 1);
        atomicAdd(&g_deg_in[dst[i]], 1);
    }
}

// Phase 1: per-thread chunk sums + rsqrt degrees + block-level scan.
__global__ void k_scan_p1(int n) {
    __shared__ int sh[SCAN_TPB];
    int t = threadIdx.x;
    int g = blockIdx.x * SCAN_TPB + t;
    int beg = g * SCAN_CHUNK;
    int end = min(beg + SCAN_CHUNK, n);
    int s = 0;
    for (int i = beg; i < end; i++) {
        int di = g_deg_in[i];
        s += di;
        g_rs_in[i]  = rsqrtf((float)max(di, 1));
        g_rs_out[i] = rsqrtf((float)max(g_deg_out[i], 1));
    }
    sh[t] = s;
    __syncthreads();
    for (int off = 1; off < SCAN_TPB; off <<= 1) {
        int v = (t >= off) ? sh[t - off] : 0;
        __syncthreads();
        sh[t] += v;
        __syncthreads();
    }
    g_tpre[g] = sh[t] - s;                       // exclusive within block
    if (t == SCAN_TPB - 1) g_bsum[blockIdx.x] = sh[t];
}

// Phase 2: one tiny block scans the 128 block sums.
__global__ void k_scan_p2() {
    __shared__ int sh[SCAN_BLOCKS];
    int t = threadIdx.x;
    int s = g_bsum[t];
    sh[t] = s;
    __syncthreads();
    for (int off = 1; off < SCAN_BLOCKS; off <<= 1) {
        int v = (t >= off) ? sh[t - off] : 0;
        __syncthreads();
        sh[t] += v;
        __syncthreads();
    }
    g_bpre[t] = sh[t] - s;                       // exclusive
}

// Phase 3: compose prefixes, write row_ptr.
__global__ void k_scan_p3(int n) {
    int t = threadIdx.x;
    int g = blockIdx.x * SCAN_TPB + t;
    int beg = g * SCAN_CHUNK;
    int end = min(beg + SCAN_CHUNK, n);
    int base = g_bpre[blockIdx.x] + g_tpre[g];
    for (int i = beg; i < end; i++) { g_row_ptr[i] = base; base += g_deg_in[i]; }
    if (end == n && beg < n) g_row_ptr[n] = base;
}

// Scatter edges into CSR slots; pack source index + its out-degree scale.
__global__ void k_scatter(const int* __restrict__ src, const int* __restrict__ dst, int e) {
    int i = blockIdx.x * blockDim.x + threadIdx.x;
    if (i < e) {
        int d = dst[i];
        int s = src[i];
        int p = g_row_ptr[d] + atomicAdd(&g_fill[d], 1);
        g_edge[p] = make_int2(s, __float_as_int(g_rs_out[s]));
    }
}

// ---------------- pull-mode SpMM ----------------
// m[v] = rs_in[v] * sum_{u in N_in(v)} rs_out[u] * f(in[u])
// USE_X=1: f = identity, in = x (conv 1).
// USE_X=0: f = relu(bn(.)) on g_h, with BN params finalized inline from g_s1/g_q1.
// One warp per node; lane owns 2 channels. Edge records read warp-uniform,
// unrolled x4 for MLP (no shfl).
template <int USE_X>
__global__ void k_spmm(const float* __restrict__ xin,
                       const float* __restrict__ gma, const float* __restrict__ bet,
                       int n) {
    const float* __restrict__ in = USE_X ? xin : g_h;
    int warp = (blockIdx.x * blockDim.x + threadIdx.x) >> 5;
    int lane = threadIdx.x & 31;
    if (warp >= n) return;

    float scx = 0.f, scy = 0.f, sfx = 0.f, sfy = 0.f;
    if (!USE_X) {
        float inv_n = 1.f / (float)n;
        int c0 = lane * 2, c1 = c0 + 1;
        float mu0 = g_s1[c0] * inv_n, mu1 = g_s1[c1] * inv_n;
        float is0 = rsqrtf(g_q1[c0] * inv_n - mu0 * mu0 + EPSV);
        float is1 = rsqrtf(g_q1[c1] * inv_n - mu1 * mu1 + EPSV);
        scx = is0 * gma[c0]; sfx = bet[c0] - mu0 * scx;
        scy = is1 * gma[c1]; sfy = bet[c1] - mu1 * scy;
    }

    int beg = g_row_ptr[warp], end = g_row_ptr[warp + 1];
    float accx = 0.f, accy = 0.f;
    int j = beg;
    for (; j + 4 <= end; j += 4) {
        int2 e0 = __ldg(&g_edge[j + 0]);
        int2 e1 = __ldg(&g_edge[j + 1]);
        int2 e2 = __ldg(&g_edge[j + 2]);
        int2 e3 = __ldg(&g_edge[j + 3]);
        float2 v0 = *(const float2*)(in + (size_t)e0.x * 64 + lane * 2);
        float2 v1 = *(const float2*)(in + (size_t)e1.x * 64 + lane * 2);
        float2 v2 = *(const float2*)(in + (size_t)e2.x * 64 + lane * 2);
        float2 v3 = *(const float2*)(in + (size_t)e3.x * 64 + lane * 2);
        if (!USE_X) {
            v0.x = fmaxf(fmaf(v0.x, scx, sfx), 0.f); v0.y = fmaxf(fmaf(v0.y, scy, sfy), 0.f);
            v1.x = fmaxf(fmaf(v1.x, scx, sfx), 0.f); v1.y = fmaxf(fmaf(v1.y, scy, sfy), 0.f);
            v2.x = fmaxf(fmaf(v2.x, scx, sfx), 0.f); v2.y = fmaxf(fmaf(v2.y, scy, sfy), 0.f);
            v3.x = fmaxf(fmaf(v3.x, scx, sfx), 0.f); v3.y = fmaxf(fmaf(v3.y, scy, sfy), 0.f);
        }
        float s0 = __int_as_float(e0.y), s1 = __int_as_float(e1.y);
        float s2 = __int_as_float(e2.y), s3 = __int_as_float(e3.y);
        accx = fmaf(s0, v0.x, accx); accy = fmaf(s0, v0.y, accy);
        accx = fmaf(s1, v1.x, accx); accy = fmaf(s1, v1.y, accy);
        accx = fmaf(s2, v2.x, accx); accy = fmaf(s2, v2.y, accy);
        accx = fmaf(s3, v3.x, accx); accy = fmaf(s3, v3.y, accy);
    }
    for (; j < end; j++) {
        int2 e0 = __ldg(&g_edge[j]);
        float2 v0 = *(const float2*)(in + (size_t)e0.x * 64 + lane * 2);
        if (!USE_X) {
            v0.x = fmaxf(fmaf(v0.x, scx, sfx), 0.f);
            v0.y = fmaxf(fmaf(v0.y, scy, sfy), 0.f);
        }
        float s0 = __int_as_float(e0.y);
        accx = fmaf(s0, v0.x, accx); accy = fmaf(s0, v0.y, accy);
    }
    float ri = g_rs_in[warp];
    *(float2*)(g_m + (size_t)warp * 64 + lane * 2) = make_float2(accx * ri, accy * ri);
}

// ---------------- f32x2 GEMM (g_m @ W + b -> g_h) with fused BN statistics ----------------
// Block 256 thr covers 64 rows. Thread: jg=t&15 owns cols {jg, jg+16, jg+32, jg+48},
// rslot=t>>4 owns rows blk*64+rslot*4 .. +3. K vectorized in pairs via fma.rn.f32x2:
// m loaded as u64 (LDG.64 == packed pair), W transposed in padded shared.
__global__ void k_gemm(const float* __restrict__ W, const float* __restrict__ bias,
                       float* __restrict__ sumbuf, float* __restrict__ sqbuf, int n) {
    __shared__ float Wt[64][66];       // [col][k], pad 2: bank = (66c+2k2)%32 = (2c+2k2)%32
    __shared__ float s_sum[16][64];
    __shared__ float s_sq[16][64];
    int t = threadIdx.x;
    for (int idx = t; idx < 4096; idx += 256) {
        int k = idx >> 6, jj = idx & 63;
        Wt[jj][k] = W[idx];
    }
    __syncthreads();

    int jg = t & 15, rslot = t >> 4;
    int row0 = blockIdx.x * 64 + rslot * 4;

    const ull* m0 = (const ull*)(g_m + (size_t)(row0 + 0) * 64);
    const ull* m1 = (const ull*)(g_m + (size_t)(row0 + 1) * 64);
    const ull* m2p = (const ull*)(g_m + (size_t)(row0 + 2) * 64);
    const ull* m3 = (const ull*)(g_m + (size_t)(row0 + 3) * 64);
    bool val0 = row0 + 0 < n, val1 = row0 + 1 < n, val2 = row0 + 2 < n, val3 = row0 + 3 < n;

    ull acc[4][4];
    #pragma unroll
    for (int r = 0; r < 4; r++)
        #pragma unroll
        for (int i = 0; i < 4; i++) acc[r][i] = 0ULL;

    #pragma unroll 4
    for (int k2 = 0; k2 < 32; k2++) {
        ull a0 = val0 ? m0[k2] : 0ULL;
        ull a1 = val1 ? m1[k2] : 0ULL;
        ull a2 = val2 ? m2p[k2] : 0ULL;
        ull a3 = val3 ? m3[k2] : 0ULL;
        #pragma unroll
        for (int i = 0; i < 4; i++) {
            ull w2 = *(const ull*)&Wt[jg + 16 * i][k2 * 2];
            acc[0][i] = f2fma(a0, w2, acc[0][i]);
            acc[1][i] = f2fma(a1, w2, acc[1][i]);
            acc[2][i] = f2fma(a2, w2, acc[2][i]);
            acc[3][i] = f2fma(a3, w2, acc[3][i]);
        }
    }

    float ls[4] = {0, 0, 0, 0}, lq[4] = {0, 0, 0, 0};
    bool vr[4] = {val0, val1, val2, val3};
    #pragma unroll
    for (int r = 0; r < 4; r++) {
        if (vr[r]) {
            int row = row0 + r;
            #pragma unroll
            for (int i = 0; i < 4; i++) {
                int c = jg + 16 * i;
                float lo, hi;
                f2unpack(acc[r][i], lo, hi);
                float v = lo + hi + bias[c];
                g_h[(size_t)row * 64 + c] = v;
                ls[i] += v;
                lq[i] += v * v;
            }
        }
    }
    #pragma unroll
    for (int i = 0; i < 4; i++) {
        int c = jg + 16 * i;
        s_sum[rslot][c] = ls[i];
        s_sq[rslot][c]  = lq[i];
    }
    __syncthreads();
    if (t < 64) {
        float a = 0, q = 0;
        #pragma unroll
        for (int r = 0; r < 16; r++) { a += s_sum[r][t]; q += s_sq[r][t]; }
        atomicAdd(&sumbuf[t], a);
        atomicAdd(&sqbuf[t], q);
    }
}

// Conv-2 readout: per-channel column sums of relu(bn(g_h)); BN finalized inline.
__global__ void k_colsum(const float* __restrict__ gma, const float* __restrict__ bet, int n) {
    int cg = threadIdx.x & 15;
    int rl = threadIdx.x >> 4;
    float inv_n = 1.f / (float)n;
    float4 gm4 = ((const float4*)gma)[cg];
    float4 be4 = ((const float4*)bet)[cg];
    float4 s4  = ((const float4*)g_s2)[cg];
    float4 q4  = ((const float4*)g_q2)[cg];
    float4 mu4, is4;
    mu4.x = s4.x * inv_n; is4.x = rsqrtf(q4.x * inv_n - mu4.x * mu4.x + EPSV);
    mu4.y = s4.y * inv_n; is4.y = rsqrtf(q4.y * inv_n - mu4.y * mu4.y + EPSV);
    mu4.z = s4.z * inv_n; is4.z = rsqrtf(q4.z * inv_n - mu4.z * mu4.z + EPSV);
    mu4.w = s4.w * inv_n; is4.w = rsqrtf(q4.w * inv_n - mu4.w * mu4.w + EPSV);
    float4 sc, sf;
    sc.x = is4.x * gm4.x; sf.x = be4.x - mu4.x * sc.x;
    sc.y = is4.y * gm4.y; sf.y = be4.y - mu4.y * sc.y;
    sc.z = is4.z * gm4.z; sf.z = be4.z - mu4.z * sc.z;
    sc.w = is4.w * gm4.w; sf.w = be4.w - mu4.w * sc.w;

    float4 acc = make_float4(0.f, 0.f, 0.f, 0.f);
    for (int row = blockIdx.x * 16 + rl; row < n; row += gridDim.x * 16) {
        float4 h = ((const float4*)(g_h + (size_t)row * 64))[cg];
        acc.x += fmaxf(fmaf(h.x, sc.x, sf.x), 0.f);
        acc.y += fmaxf(fmaf(h.y, sc.y, sf.y), 0.f);
        acc.z += fmaxf(fmaf(h.z, sc.z, sf.z), 0.f);
        acc.w += fmaxf(fmaf(h.w, sc.w, sf.w), 0.f);
    }
    __shared__ float s[16][64];
    s[rl][cg * 4 + 0] = acc.x; s[rl][cg * 4 + 1] = acc.y;
    s[rl][cg * 4 + 2] = acc.z; s[rl][cg * 4 + 3] = acc.w;
    __syncthreads();
    if (threadIdx.x < 64) {
        float tsum = 0;
        #pragma unroll
        for (int r = 0; r < 16; r++) tsum += s[r][threadIdx.x];
        atomicAdd(&g_colsum[threadIdx.x], tsum);
    }
}

// Final readout: out[j] = bc[j] + sum_k (colsum[k]/n) * Wc[k][j]
__global__ void k_final(const float* __restrict__ Wc, const float* __restrict__ bc,
                        float* __restrict__ out, int n) {
    __shared__ float s0[64], s1[64];
    int t = threadIdx.x;
    float v = g_colsum[t] / (float)n;
    s0[t] = v * Wc[t * 2 + 0];
    s1[t] = v * Wc[t * 2 + 1];
    __syncthreads();
    if (t == 0) {
        float a = 0.f, b = 0.f;
        for (int k = 0; k < 64; k++) { a += s0[k]; b += s1[k]; }
        out[0] = a + bc[0];
        out[1] = b + bc[1];
    }
}

// ---------------- launch ----------------
extern "C" void kernel_launch(void* const* d_in, const int* in_sizes, int n_in,
                              void* d_out, int out_size) {
    const float* x   = (const float*)d_in[0];
    const int*   src = (const int*)d_in[1];
    const int*   dst = (const int*)d_in[2];
    const float* W1  = (const float*)d_in[3];
    const float* b1  = (const float*)d_in[4];
    const float* g1  = (const float*)d_in[5];
    const float* be1 = (const float*)d_in[6];
    const float* W2  = (const float*)d_in[7];
    const float* b2  = (const float*)d_in[8];
    const float* g2  = (const float*)d_in[9];
    const float* be2 = (const float*)d_in[10];
    const float* Wc  = (const float*)d_in[11];
    const float* bc  = (const float*)d_in[12];
    float* out = (float*)d_out;

    int n = in_sizes[0] / 64;
    int e = in_sizes[1];

    int nb = (n + 255) / 256;
    int eb = (e + 255) / 256;
    int spmm_blocks = (n + 7) / 8;       // 8 warps per 256-thread block
    int gemm_blocks = (n + 63) / 64;

    float* ds1; cudaGetSymbolAddress((void**)&ds1, g_s1);
    float* dq1; cudaGetSymbolAddress((void**)&dq1, g_q1);
    float* ds2; cudaGetSymbolAddress((void**)&ds2, g_s2);
    float* dq2; cudaGetSymbolAddress((void**)&dq2, g_q2);

    // graph preprocessing (CSR by dst) — reused by both convs
    k_zero_graph<<<nb, 256>>>(n);
    k_deg<<<eb, 256>>>(src, dst, e);
    k_scan_p1<<<SCAN_BLOCKS, SCAN_TPB>>>(n);
    k_scan_p2<<<1, SCAN_BLOCKS>>>();
    k_scan_p3<<<SCAN_BLOCKS, SCAN_TPB>>>(n);
    k_scatter<<<eb, 256>>>(src, dst, e);

    // conv 1
    k_spmm<1><<<spmm_blocks, 256>>>(x, nullptr, nullptr, n);
    k_gemm<<<gemm_blocks, 256>>>(W1, b1, ds1, dq1, n);

    // conv 2 (BN+ReLU of conv-1 fused into this SpMM, stats finalized inline)
    k_spmm<0><<<spmm_blocks, 256>>>(nullptr, g1, be1, n);
    k_gemm<<<gemm_blocks, 256>>>(W2, b2, ds2, dq2, n);

    // readout + classifier
    k_colsum<<<512, 256>>>(g2, be2, n);
    k_final<<<1, 64>>>(Wc, bc, out, n);
    (void)n_in; (void)out_size;
}

// round 7
// speedup vs baseline: 1.6745x; 1.1109x over previous
#include <cuda_runtime.h>
#include <cuda_bf16.h>

// CoPEModel GCN on GB300.
// CSR-build (memset blob + 2-kernel scan) + bf16-gather pull-mode SpMM +
// f32x2 GEMM with fused BN stats + fused colsum/readout.
// Inputs (metadata order): x, src, dst, W1, b1, g1, be1, W2, b2, g2, be2, Wc, bc
// Output: [1,2] float32.

#define NMAX 100000
#define EMAX 1600000

#define SCAN_BLOCKS 128
#define SCAN_TPB    256
#define SCAN_T      (SCAN_BLOCKS * SCAN_TPB)   // 32768 scan threads
#define SCAN_CHUNK  4                          // ceil(100000/32768)

#define EPSV 1e-5f

typedef unsigned long long ull;

// ---- zero-initialized-per-launch blob (single memset node) ----
// [0,N): deg_out  [N,2N): deg_in  [2N..): s1,q1,s2,q2,colsum,done
#define OFF_DEG_OUT 0
#define OFF_DEG_IN  NMAX
#define OFF_STATS   (2 * NMAX)
#define BLOB_INTS   (2 * NMAX + 384)
__device__ __align__(16) int g_blob[BLOB_INTS];

__device__ __align__(16) float g_rs_out[NMAX];
__device__ __align__(16) float g_rs_in[NMAX];
__device__ __align__(16) int   g_row_ptr[NMAX + 1];
__device__ __align__(16) int   g_fill[NMAX];            // scatter cursors (init by scan p3)
__device__ __align__(16) int2  g_edge[EMAX];            // {src, bits(rs_out[src])}
__device__ __align__(16) int   g_tpre[SCAN_T];
__device__ __align__(16) int   g_bsum[SCAN_BLOCKS];
__device__ __align__(16) __nv_bfloat162 g_xb[(size_t)NMAX * 32];  // bf16 x
__device__ __align__(16) __nv_bfloat162 g_ab[(size_t)NMAX * 32];  // bf16 relu(bn(h1))
__device__ __align__(16) float g_m[(size_t)NMAX * 64];  // aggregated messages
__device__ __align__(16) float g_h[(size_t)NMAX * 64];  // post-GEMM

// ---------------- f32x2 helpers ----------------
__device__ __forceinline__ void f2unpack(ull v, float& a, float& b) {
    asm("mov.b64 {%0, %1}, %2;" : "=f"(a), "=f"(b) : "l"(v));
}
__device__ __forceinline__ ull f2fma(ull a, ull b, ull c) {
    ull d; asm("fma.rn.f32x2 %0, %1, %2, %3;" : "=l"(d) : "l"(a), "l"(b), "l"(c)); return d;
}

// ---------------- graph preprocessing ----------------

__global__ void k_deg(const int* __restrict__ src, const int* __restrict__ dst, int e) {
    int i = blockIdx.x * blockDim.x + threadIdx.x;
    if (i < e) {
        atomicAdd(&g_blob[OFF_DEG_OUT + src[i]], 1);
        atomicAdd(&g_blob[OFF_DEG_IN + dst[i]], 1);
    }
}

// Phase 1: per-thread chunk sums + rsqrt degrees + block-level scan.
__global__ void k_scan_p1(int n) {
    __shared__ int sh[SCAN_TPB];
    int t = threadIdx.x;
    int g = blockIdx.x * SCAN_TPB + t;
    int beg = g * SCAN_CHUNK;
    int end = min(beg + SCAN_CHUNK, n);
    int s = 0;
    for (int i = beg; i < end; i++) {
        int di = g_blob[OFF_DEG_IN + i];
        s += di;
        g_rs_in[i]  = rsqrtf((float)max(di, 1));
        g_rs_out[i] = rsqrtf((float)max(g_blob[OFF_DEG_OUT + i], 1));
    }
    sh[t] = s;
    __syncthreads();
    for (int off = 1; off < SCAN_TPB; off <<= 1) {
        int v = (t >= off) ? sh[t - off] : 0;
        __syncthreads();
        sh[t] += v;
        __syncthreads();
    }
    g_tpre[g] = sh[t] - s;
    if (t == SCAN_TPB - 1) g_bsum[blockIdx.x] = sh[t];
}

// Phase 3 (phase 2 inlined): each block reduces its block-sum prefix, writes
// row_ptr AND the scatter cursor copy.
__global__ void k_scan_p3(int n) {
    __shared__ int sb[SCAN_BLOCKS];
    int t = threadIdx.x;
    if (t < SCAN_BLOCKS) sb[t] = (t < blockIdx.x) ? g_bsum[t] : 0;
    __syncthreads();
    for (int off = SCAN_BLOCKS / 2; off >= 1; off >>= 1) {
        if (t < off) sb[t] += sb[t + off];
        __syncthreads();
    }
    int bpre = sb[0];
    int g = blockIdx.x * SCAN_TPB + t;
    int beg = g * SCAN_CHUNK;
    int end = min(beg + SCAN_CHUNK, n);
    int base = bpre + g_tpre[g];
    for (int i = beg; i < end; i++) {
        g_row_ptr[i] = base;
        g_fill[i] = base;
        base += g_blob[OFF_DEG_IN + i];
    }
    if (end == n && beg < n) g_row_ptr[n] = base;
}

// Scatter edges into CSR slots using cursor copies; pack src + rs_out[src].
__global__ void k_scatter(const int* __restrict__ src, const int* __restrict__ dst, int e) {
    int i = blockIdx.x * blockDim.x + threadIdx.x;
    if (i < e) {
        int d = dst[i];
        int s = src[i];
        int p = atomicAdd(&g_fill[d], 1);
        g_edge[p] = make_int2(s, __float_as_int(g_rs_out[s]));
    }
}

// ---------------- bf16 conversion passes ----------------

// x (fp32) -> g_xb (bf16). n*16 float4 elements.
__global__ void k_x2bf(const float* __restrict__ x, int n16) {
    int i = blockIdx.x * blockDim.x + threadIdx.x;
    int stride = gridDim.x * blockDim.x;
    const float4* x4 = (const float4*)x;
    uint2* ob = (uint2*)g_xb;
    for (; i < n16; i += stride) {
        float4 f = x4[i];
        __nv_bfloat162 lo = __floats2bfloat162_rn(f.x, f.y);
        __nv_bfloat162 hi = __floats2bfloat162_rn(f.z, f.w);
        uint2 v;
        v.x = *(unsigned*)&lo;
        v.y = *(unsigned*)&hi;
        ob[i] = v;
    }
}

// relu(bn(g_h)) -> g_ab (bf16), conv-1 epilogue. BN finalized inline from s1/q1.
// grid*block multiple of 16 so each thread's channel group is fixed.
__global__ void k_actbf(const float* __restrict__ s1, const float* __restrict__ q1,
                        const float* __restrict__ gma, const float* __restrict__ bet,
                        int n) {
    int i = blockIdx.x * blockDim.x + threadIdx.x;
    int stride = gridDim.x * blockDim.x;
    int cg = i & 15;
    float inv_n = 1.f / (float)n;
    float sc[4], sf[4];
    #pragma unroll
    for (int k = 0; k < 4; k++) {
        int c = cg * 4 + k;
        float mu = s1[c] * inv_n;
        float is = rsqrtf(q1[c] * inv_n - mu * mu + EPSV);
        sc[k] = is * gma[c];
        sf[k] = bet[c] - mu * sc[k];
    }
    const float4* h4 = (const float4*)g_h;
    uint2* ob = (uint2*)g_ab;
    int n16 = n * 16;
    for (; i < n16; i += stride) {
        float4 h = h4[i];
        float y0 = fmaxf(fmaf(h.x, sc[0], sf[0]), 0.f);
        float y1 = fmaxf(fmaf(h.y, sc[1], sf[1]), 0.f);
        float y2 = fmaxf(fmaf(h.z, sc[2], sf[2]), 0.f);
        float y3 = fmaxf(fmaf(h.w, sc[3], sf[3]), 0.f);
        __nv_bfloat162 lo = __floats2bfloat162_rn(y0, y1);
        __nv_bfloat162 hi = __floats2bfloat162_rn(y2, y3);
        uint2 v;
        v.x = *(unsigned*)&lo;
        v.y = *(unsigned*)&hi;
        ob[i] = v;
    }
}

// ---------------- pull-mode SpMM (bf16 gather, fp32 accumulate) ----------------
// m[v] = rs_in[v] * sum_{u in N_in(v)} rs_out[u] * in[u]
// WHICH=0 reads g_xb (conv 1), WHICH=1 reads g_ab (conv 2). Scratch arrays are
// referenced in DEVICE code only (host-side symbol names are not device ptrs!).
// One warp per node; lane owns 2 channels. Constant 8-wide predicated batches.
template <int WHICH>
__global__ void k_spmm(int n) {
    const __nv_bfloat162* __restrict__ in = WHICH ? g_ab : g_xb;
    int warp = (blockIdx.x * blockDim.x + threadIdx.x) >> 5;
    int lane = threadIdx.x & 31;
    if (warp >= n) return;

    int beg = g_row_ptr[warp], end = g_row_ptr[warp + 1];
    float accx = 0.f, accy = 0.f;
    for (int j = beg; j < end; j += 8) {
        int2 e[8];
        #pragma unroll
        for (int i = 0; i < 8; i++) {
            int idx = j + i;
            e[i] = (idx < end) ? __ldg(&g_edge[idx]) : make_int2(0, 0);
        }
        float2 v[8];
        #pragma unroll
        for (int i = 0; i < 8; i++) {
            __nv_bfloat162 b = __ldg(&in[(size_t)e[i].x * 32 + lane]);
            v[i] = __bfloat1622float2(b);
        }
        #pragma unroll
        for (int i = 0; i < 8; i++) {
            float s = __int_as_float(e[i].y);
            accx = fmaf(s, v[i].x, accx);
            accy = fmaf(s, v[i].y, accy);
        }
    }
    float ri = g_rs_in[warp];
    *(float2*)(g_m + (size_t)warp * 64 + lane * 2) = make_float2(accx * ri, accy * ri);
}

// ---------------- f32x2 GEMM (g_m @ W + b -> g_h) with fused BN statistics ----------------
__global__ void k_gemm(const float* __restrict__ W, const float* __restrict__ bias,
                       float* __restrict__ sumbuf, float* __restrict__ sqbuf, int n) {
    __shared__ float Wt[64][66];
    __shared__ float s_sum[16][64];
    __shared__ float s_sq[16][64];
    int t = threadIdx.x;
    for (int idx = t; idx < 4096; idx += 256) {
        int k = idx >> 6, jj = idx & 63;
        Wt[jj][k] = W[idx];
    }
    __syncthreads();

    int jg = t & 15, rslot = t >> 4;
    int row0 = blockIdx.x * 64 + rslot * 4;

    const ull* m0 = (const ull*)(g_m + (size_t)(row0 + 0) * 64);
    const ull* m1 = (const ull*)(g_m + (size_t)(row0 + 1) * 64);
    const ull* m2p = (const ull*)(g_m + (size_t)(row0 + 2) * 64);
    const ull* m3 = (const ull*)(g_m + (size_t)(row0 + 3) * 64);
    bool val0 = row0 + 0 < n, val1 = row0 + 1 < n, val2 = row0 + 2 < n, val3 = row0 + 3 < n;

    ull acc[4][4];
    #pragma unroll
    for (int r = 0; r < 4; r++)
        #pragma unroll
        for (int i = 0; i < 4; i++) acc[r][i] = 0ULL;

    #pragma unroll 4
    for (int k2 = 0; k2 < 32; k2++) {
        ull a0 = val0 ? m0[k2] : 0ULL;
        ull a1 = val1 ? m1[k2] : 0ULL;
        ull a2 = val2 ? m2p[k2] : 0ULL;
        ull a3 = val3 ? m3[k2] : 0ULL;
        #pragma unroll
        for (int i = 0; i < 4; i++) {
            ull w2 = *(const ull*)&Wt[jg + 16 * i][k2 * 2];
            acc[0][i] = f2fma(a0, w2, acc[0][i]);
            acc[1][i] = f2fma(a1, w2, acc[1][i]);
            acc[2][i] = f2fma(a2, w2, acc[2][i]);
            acc[3][i] = f2fma(a3, w2, acc[3][i]);
        }
    }

    float ls[4] = {0, 0, 0, 0}, lq[4] = {0, 0, 0, 0};
    bool vr[4] = {val0, val1, val2, val3};
    #pragma unroll
    for (int r = 0; r < 4; r++) {
        if (vr[r]) {
            int row = row0 + r;
            #pragma unroll
            for (int i = 0; i < 4; i++) {
                int c = jg + 16 * i;
                float lo, hi;
                f2unpack(acc[r][i], lo, hi);
                float v = lo + hi + bias[c];
                g_h[(size_t)row * 64 + c] = v;
                ls[i] += v;
                lq[i] += v * v;
            }
        }
    }
    #pragma unroll
    for (int i = 0; i < 4; i++) {
        int c = jg + 16 * i;
        s_sum[rslot][c] = ls[i];
        s_sq[rslot][c]  = lq[i];
    }
    __syncthreads();
    if (t < 64) {
        float a = 0, q = 0;
        #pragma unroll
        for (int r = 0; r < 16; r++) { a += s_sum[r][t]; q += s_sq[r][t]; }
        atomicAdd(&sumbuf[t], a);
        atomicAdd(&sqbuf[t], q);
    }
}

// ---------------- fused conv-2 readout + classifier ----------------
__global__ void k_colsum_final(const float* __restrict__ s2, const float* __restrict__ q2,
                               const float* __restrict__ gma, const float* __restrict__ bet,
                               float* __restrict__ colsum, int* __restrict__ done,
                               const float* __restrict__ Wc, const float* __restrict__ bc,
                               float* __restrict__ out, int n) {
    int cg = threadIdx.x & 15;
    int rl = threadIdx.x >> 4;
    float inv_n = 1.f / (float)n;
    float4 gm4 = ((const float4*)gma)[cg];
    float4 be4 = ((const float4*)bet)[cg];
    float4 s4  = ((const float4*)s2)[cg];
    float4 q4  = ((const float4*)q2)[cg];
    float4 mu4, is4;
    mu4.x = s4.x * inv_n; is4.x = rsqrtf(q4.x * inv_n - mu4.x * mu4.x + EPSV);
    mu4.y = s4.y * inv_n; is4.y = rsqrtf(q4.y * inv_n - mu4.y * mu4.y + EPSV);
    mu4.z = s4.z * inv_n; is4.z = rsqrtf(q4.z * inv_n - mu4.z * mu4.z + EPSV);
    mu4.w = s4.w * inv_n; is4.w = rsqrtf(q4.w * inv_n - mu4.w * mu4.w + EPSV);
    float4 sc, sf;
    sc.x = is4.x * gm4.x; sf.x = be4.x - mu4.x * sc.x;
    sc.y = is4.y * gm4.y; sf.y = be4.y - mu4.y * sc.y;
    sc.z = is4.z * gm4.z; sf.z = be4.z - mu4.z * sc.z;
    sc.w = is4.w * gm4.w; sf.w = be4.w - mu4.w * sc.w;

    float4 acc = make_float4(0.f, 0.f, 0.f, 0.f);
    for (int row = blockIdx.x * 16 + rl; row < n; row += gridDim.x * 16) {
        float4 h = ((const float4*)(g_h + (size_t)row * 64))[cg];
        acc.x += fmaxf(fmaf(h.x, sc.x, sf.x), 0.f);
        acc.y += fmaxf(fmaf(h.y, sc.y, sf.y), 0.f);
        acc.z += fmaxf(fmaf(h.z, sc.z, sf.z), 0.f);
        acc.w += fmaxf(fmaf(h.w, sc.w, sf.w), 0.f);
    }
    __shared__ float s[16][64];
    s[rl][cg * 4 + 0] = acc.x; s[rl][cg * 4 + 1] = acc.y;
    s[rl][cg * 4 + 2] = acc.z; s[rl][cg * 4 + 3] = acc.w;
    __syncthreads();
    if (threadIdx.x < 64) {
        float tsum = 0;
        #pragma unroll
        for (int r = 0; r < 16; r++) tsum += s[r][threadIdx.x];
        atomicAdd(&colsum[threadIdx.x], tsum);
    }
    __threadfence();
    __syncthreads();
    __shared__ int is_last;
    if (threadIdx.x == 0) {
        int prev = atomicAdd(done, 1);
        is_last = (prev == gridDim.x - 1);
    }
    __syncthreads();
    if (is_last) {
        __shared__ float s0[64], s1[64];
        if (threadIdx.x < 64) {
            int t = threadIdx.x;
            float v = atomicAdd(&colsum[t], 0.0f) * inv_n;   // L2-coherent read
            s0[t] = v * Wc[t * 2 + 0];
            s1[t] = v * Wc[t * 2 + 1];
        }
        __syncthreads();
        if (threadIdx.x == 0) {
            float a = 0.f, b = 0.f;
            for (int k = 0; k < 64; k++) { a += s0[k]; b += s1[k]; }
            out[0] = a + bc[0];
            out[1] = b + bc[1];
        }
    }
}

// ---------------- launch ----------------
extern "C" void kernel_launch(void* const* d_in, const int* in_sizes, int n_in,
                              void* d_out, int out_size) {
    const float* x   = (const float*)d_in[0];
    const int*   src = (const int*)d_in[1];
    const int*   dst = (const int*)d_in[2];
    const float* W1  = (const float*)d_in[3];
    const float* b1  = (const float*)d_in[4];
    const float* g1  = (const float*)d_in[5];
    const float* be1 = (const float*)d_in[6];
    const float* W2  = (const float*)d_in[7];
    const float* b2  = (const float*)d_in[8];
    const float* g2  = (const float*)d_in[9];
    const float* be2 = (const float*)d_in[10];
    const float* Wc  = (const float*)d_in[11];
    const float* bc  = (const float*)d_in[12];
    float* out = (float*)d_out;

    int n = in_sizes[0] / 64;
    int e = in_sizes[1];

    int eb = (e + 255) / 256;
    int spmm_blocks = (n + 7) / 8;
    int gemm_blocks = (n + 63) / 64;

    int* blob_d;
    cudaGetSymbolAddress((void**)&blob_d, g_blob);
    float* ds1  = (float*)(blob_d + OFF_STATS);
    float* dq1  = ds1 + 64;
    float* ds2  = ds1 + 128;
    float* dq2  = ds1 + 192;
    float* dcol = ds1 + 256;
    int*   ddone = blob_d + OFF_STATS + 320;

    // zero degrees + stats + counter in one memset node
    cudaMemsetAsync(blob_d, 0, (size_t)BLOB_INTS * sizeof(int));

    // graph preprocessing (CSR by dst) — reused by both convs
    k_deg<<<eb, 256>>>(src, dst, e);
    k_scan_p1<<<SCAN_BLOCKS, SCAN_TPB>>>(n);
    k_scan_p3<<<SCAN_BLOCKS, SCAN_TPB>>>(n);
    k_scatter<<<eb, 256>>>(src, dst, e);

    // conv 1 (bf16 gather of x)
    k_x2bf<<<512, 256>>>(x, n * 16);
    k_spmm<0><<<spmm_blocks, 256>>>(n);
    k_gemm<<<gemm_blocks, 256>>>(W1, b1, ds1, dq1, n);

    // conv 2 (bf16 gather of relu(bn(h1)))
    k_actbf<<<512, 256>>>(ds1, dq1, g1, be1, n);
    k_spmm<1><<<spmm_blocks, 256>>>(n);
    k_gemm<<<gemm_blocks, 256>>>(W2, b2, ds2, dq2, n);

    // fused readout + classifier
    k_colsum_final<<<512, 256>>>(ds2, dq2, g2, be2, dcol, ddone, Wc, bc, out, n);
    (void)n_in; (void)out_size;
}

// round 8
// speedup vs baseline: 1.7364x; 1.0370x over previous
#include <cuda_runtime.h>
#include <cuda_bf16.h>

// CoPEModel GCN on GB300.
// CSR-build (memset blob + 2-kernel scan) + bf16-gather pull-mode SpMM with
// rs_out pre-scaled into features (int-only edges) + f32x2 GEMM with fused BN
// stats + fused colsum/readout.
// Inputs (metadata order): x, src, dst, W1, b1, g1, be1, W2, b2, g2, be2, Wc, bc
// Output: [1,2] float32.

#define NMAX 100000
#define EMAX 1600000

#define SCAN_BLOCKS 128
#define SCAN_TPB    256
#define SCAN_T      (SCAN_BLOCKS * SCAN_TPB)   // 32768 scan threads
#define SCAN_CHUNK  4                          // ceil(100000/32768)

#define EPSV 1e-5f

typedef unsigned long long ull;

// ---- zero-initialized-per-launch blob (single memset node) ----
// [0,N): deg_out  [N,2N): deg_in  [2N..): s1,q1,s2,q2,colsum,done
#define OFF_DEG_OUT 0
#define OFF_DEG_IN  NMAX
#define OFF_STATS   (2 * NMAX)
#define BLOB_INTS   (2 * NMAX + 384)
__device__ __align__(16) int g_blob[BLOB_INTS];

__device__ __align__(16) float g_rs_out[NMAX];
__device__ __align__(16) float g_rs_in[NMAX];
__device__ __align__(16) int   g_row_ptr[NMAX + 1];
__device__ __align__(16) int   g_fill[NMAX];            // scatter cursors (init by scan p3)
__device__ __align__(16) int   g_col[EMAX];             // CSR column (src) indices
__device__ __align__(16) int   g_tpre[SCAN_T];
__device__ __align__(16) int   g_bsum[SCAN_BLOCKS];
__device__ __align__(16) __nv_bfloat162 g_xb[(size_t)NMAX * 32];  // bf16 rs_out*x
__device__ __align__(16) __nv_bfloat162 g_ab[(size_t)NMAX * 32];  // bf16 rs_out*relu(bn(h1))
__device__ __align__(16) float g_m[(size_t)NMAX * 64];  // aggregated messages
__device__ __align__(16) float g_h[(size_t)NMAX * 64];  // post-GEMM

// ---------------- f32x2 helpers ----------------
__device__ __forceinline__ void f2unpack(ull v, float& a, float& b) {
    asm("mov.b64 {%0, %1}, %2;" : "=f"(a), "=f"(b) : "l"(v));
}
__device__ __forceinline__ ull f2fma(ull a, ull b, ull c) {
    ull d; asm("fma.rn.f32x2 %0, %1, %2, %3;" : "=l"(d) : "l"(a), "l"(b), "l"(c)); return d;
}

// ---------------- graph preprocessing ----------------

__global__ void k_deg(const int* __restrict__ src, const int* __restrict__ dst, int e) {
    int i = blockIdx.x * blockDim.x + threadIdx.x;
    if (i < e) {
        atomicAdd(&g_blob[OFF_DEG_OUT + src[i]], 1);
        atomicAdd(&g_blob[OFF_DEG_IN + dst[i]], 1);
    }
}

// Phase 1: per-thread chunk sums + rsqrt degrees + block-level scan.
__global__ void k_scan_p1(int n) {
    __shared__ int sh[SCAN_TPB];
    int t = threadIdx.x;
    int g = blockIdx.x * SCAN_TPB + t;
    int beg = g * SCAN_CHUNK;
    int end = min(beg + SCAN_CHUNK, n);
    int s = 0;
    for (int i = beg; i < end; i++) {
        int di = g_blob[OFF_DEG_IN + i];
        s += di;
        g_rs_in[i]  = rsqrtf((float)max(di, 1));
        g_rs_out[i] = rsqrtf((float)max(g_blob[OFF_DEG_OUT + i], 1));
    }
    sh[t] = s;
    __syncthreads();
    for (int off = 1; off < SCAN_TPB; off <<= 1) {
        int v = (t >= off) ? sh[t - off] : 0;
        __syncthreads();
        sh[t] += v;
        __syncthreads();
    }
    g_tpre[g] = sh[t] - s;
    if (t == SCAN_TPB - 1) g_bsum[blockIdx.x] = sh[t];
}

// Phase 3 (phase 2 inlined): each block reduces its block-sum prefix, writes
// row_ptr AND the scatter cursor copy.
__global__ void k_scan_p3(int n) {
    __shared__ int sb[SCAN_BLOCKS];
    int t = threadIdx.x;
    if (t < SCAN_BLOCKS) sb[t] = (t < blockIdx.x) ? g_bsum[t] : 0;
    __syncthreads();
    for (int off = SCAN_BLOCKS / 2; off >= 1; off >>= 1) {
        if (t < off) sb[t] += sb[t + off];
        __syncthreads();
    }
    int bpre = sb[0];
    int g = blockIdx.x * SCAN_TPB + t;
    int beg = g * SCAN_CHUNK;
    int end = min(beg + SCAN_CHUNK, n);
    int base = bpre + g_tpre[g];
    for (int i = beg; i < end; i++) {
        g_row_ptr[i] = base;
        g_fill[i] = base;
        base += g_blob[OFF_DEG_IN + i];
    }
    if (end == n && beg < n) g_row_ptr[n] = base;
}

// Scatter src indices into CSR slots (4B payload, no scale gather).
__global__ void k_scatter(const int* __restrict__ src, const int* __restrict__ dst, int e) {
    int i = blockIdx.x * blockDim.x + threadIdx.x;
    if (i < e) {
        int d = dst[i];
        int p = atomicAdd(&g_fill[d], 1);
        g_col[p] = src[i];
    }
}

// ---------------- bf16 conversion passes (rs_out pre-scaled) ----------------

// rs_out[row]*x (fp32) -> g_xb (bf16). n*16 float4 elements; row = i>>4.
__global__ void k_x2bf(const float* __restrict__ x, int n16) {
    int i = blockIdx.x * blockDim.x + threadIdx.x;
    int stride = gridDim.x * blockDim.x;
    const float4* x4 = (const float4*)x;
    uint2* ob = (uint2*)g_xb;
    for (; i < n16; i += stride) {
        float ro = g_rs_out[i >> 4];
        float4 f = x4[i];
        __nv_bfloat162 lo = __floats2bfloat162_rn(f.x * ro, f.y * ro);
        __nv_bfloat162 hi = __floats2bfloat162_rn(f.z * ro, f.w * ro);
        uint2 v;
        v.x = *(unsigned*)&lo;
        v.y = *(unsigned*)&hi;
        ob[i] = v;
    }
}

// rs_out[row]*relu(bn(g_h)) -> g_ab (bf16), conv-1 epilogue, BN inline.
// grid*block multiple of 16 so each thread's channel group is fixed.
__global__ void k_actbf(const float* __restrict__ s1, const float* __restrict__ q1,
                        const float* __restrict__ gma, const float* __restrict__ bet,
                        int n) {
    int i = blockIdx.x * blockDim.x + threadIdx.x;
    int stride = gridDim.x * blockDim.x;
    int cg = i & 15;
    float inv_n = 1.f / (float)n;
    float sc[4], sf[4];
    #pragma unroll
    for (int k = 0; k < 4; k++) {
        int c = cg * 4 + k;
        float mu = s1[c] * inv_n;
        float is = rsqrtf(q1[c] * inv_n - mu * mu + EPSV);
        sc[k] = is * gma[c];
        sf[k] = bet[c] - mu * sc[k];
    }
    const float4* h4 = (const float4*)g_h;
    uint2* ob = (uint2*)g_ab;
    int n16 = n * 16;
    for (; i < n16; i += stride) {
        float ro = g_rs_out[i >> 4];
        float4 h = h4[i];
        float y0 = fmaxf(fmaf(h.x, sc[0], sf[0]), 0.f) * ro;
        float y1 = fmaxf(fmaf(h.y, sc[1], sf[1]), 0.f) * ro;
        float y2 = fmaxf(fmaf(h.z, sc[2], sf[2]), 0.f) * ro;
        float y3 = fmaxf(fmaf(h.w, sc[3], sf[3]), 0.f) * ro;
        __nv_bfloat162 lo = __floats2bfloat162_rn(y0, y1);
        __nv_bfloat162 hi = __floats2bfloat162_rn(y2, y3);
        uint2 v;
        v.x = *(unsigned*)&lo;
        v.y = *(unsigned*)&hi;
        ob[i] = v;
    }
}

// ---------------- pull-mode SpMM (bf16 gather, fp32 accumulate) ----------------
// m[v] = rs_in[v] * sum_{u in N_in(v)} in[u]   (rs_out already folded into in)
// WHICH=0 reads g_xb (conv 1), WHICH=1 reads g_ab (conv 2). Scratch arrays
// referenced in DEVICE code only. One warp per node; lane owns 2 channels.
// 8-wide full batches + scalar remainder.
template <int WHICH>
__global__ void k_spmm(int n) {
    const __nv_bfloat162* __restrict__ in = WHICH ? g_ab : g_xb;
    int warp = (blockIdx.x * blockDim.x + threadIdx.x) >> 5;
    int lane = threadIdx.x & 31;
    if (warp >= n) return;

    int beg = g_row_ptr[warp], end = g_row_ptr[warp + 1];
    float accx = 0.f, accy = 0.f;
    int j = beg;
    for (; j + 8 <= end; j += 8) {
        int u[8];
        #pragma unroll
        for (int i = 0; i < 8; i++) u[i] = __ldg(&g_col[j + i]);
        float2 v[8];
        #pragma unroll
        for (int i = 0; i < 8; i++) {
            __nv_bfloat162 b = __ldg(&in[(size_t)u[i] * 32 + lane]);
            v[i] = __bfloat1622float2(b);
        }
        #pragma unroll
        for (int i = 0; i < 8; i++) {
            accx += v[i].x;
            accy += v[i].y;
        }
    }
    for (; j < end; j++) {
        int u = __ldg(&g_col[j]);
        __nv_bfloat162 b = __ldg(&in[(size_t)u * 32 + lane]);
        float2 v = __bfloat1622float2(b);
        accx += v.x;
        accy += v.y;
    }
    float ri = g_rs_in[warp];
    *(float2*)(g_m + (size_t)warp * 64 + lane * 2) = make_float2(accx * ri, accy * ri);
}

// ---------------- f32x2 GEMM (g_m @ W + b -> g_h) with fused BN statistics ----------------
__global__ void k_gemm(const float* __restrict__ W, const float* __restrict__ bias,
                       float* __restrict__ sumbuf, float* __restrict__ sqbuf, int n) {
    __shared__ float Wt[64][66];
    __shared__ float s_sum[16][64];
    __shared__ float s_sq[16][64];
    int t = threadIdx.x;
    for (int idx = t; idx < 4096; idx += 256) {
        int k = idx >> 6, jj = idx & 63;
        Wt[jj][k] = W[idx];
    }
    __syncthreads();

    int jg = t & 15, rslot = t >> 4;
    int row0 = blockIdx.x * 64 + rslot * 4;

    const ull* m0 = (const ull*)(g_m + (size_t)(row0 + 0) * 64);
    const ull* m1 = (const ull*)(g_m + (size_t)(row0 + 1) * 64);
    const ull* m2p = (const ull*)(g_m + (size_t)(row0 + 2) * 64);
    const ull* m3 = (const ull*)(g_m + (size_t)(row0 + 3) * 64);
    bool val0 = row0 + 0 < n, val1 = row0 + 1 < n, val2 = row0 + 2 < n, val3 = row0 + 3 < n;

    ull acc[4][4];
    #pragma unroll
    for (int r = 0; r < 4; r++)
        #pragma unroll
        for (int i = 0; i < 4; i++) acc[r][i] = 0ULL;

    #pragma unroll 4
    for (int k2 = 0; k2 < 32; k2++) {
        ull a0 = val0 ? m0[k2] : 0ULL;
        ull a1 = val1 ? m1[k2] : 0ULL;
        ull a2 = val2 ? m2p[k2] : 0ULL;
        ull a3 = val3 ? m3[k2] : 0ULL;
        #pragma unroll
        for (int i = 0; i < 4; i++) {
            ull w2 = *(const ull*)&Wt[jg + 16 * i][k2 * 2];
            acc[0][i] = f2fma(a0, w2, acc[0][i]);
            acc[1][i] = f2fma(a1, w2, acc[1][i]);
            acc[2][i] = f2fma(a2, w2, acc[2][i]);
            acc[3][i] = f2fma(a3, w2, acc[3][i]);
        }
    }

    float ls[4] = {0, 0, 0, 0}, lq[4] = {0, 0, 0, 0};
    bool vr[4] = {val0, val1, val2, val3};
    #pragma unroll
    for (int r = 0; r < 4; r++) {
        if (vr[r]) {
            int row = row0 + r;
            #pragma unroll
            for (int i = 0; i < 4; i++) {
                int c = jg + 16 * i;
                float lo, hi;
                f2unpack(acc[r][i], lo, hi);
                float v = lo + hi + bias[c];
                g_h[(size_t)row * 64 + c] = v;
                ls[i] += v;
                lq[i] += v * v;
            }
        }
    }
    #pragma unroll
    for (int i = 0; i < 4; i++) {
        int c = jg + 16 * i;
        s_sum[rslot][c] = ls[i];
        s_sq[rslot][c]  = lq[i];
    }
    __syncthreads();
    if (t < 64) {
        float a = 0, q = 0;
        #pragma unroll
        for (int r = 0; r < 16; r++) { a += s_sum[r][t]; q += s_sq[r][t]; }
        atomicAdd(&sumbuf[t], a);
        atomicAdd(&sqbuf[t], q);
    }
}

// ---------------- fused conv-2 readout + classifier ----------------
__global__ void k_colsum_final(const float* __restrict__ s2, const float* __restrict__ q2,
                               const float* __restrict__ gma, const float* __restrict__ bet,
                               float* __restrict__ colsum, int* __restrict__ done,
                               const float* __restrict__ Wc, const float* __restrict__ bc,
                               float* __restrict__ out, int n) {
    int cg = threadIdx.x & 15;
    int rl = threadIdx.x >> 4;
    float inv_n = 1.f / (float)n;
    float4 gm4 = ((const float4*)gma)[cg];
    float4 be4 = ((const float4*)bet)[cg];
    float4 s4  = ((const float4*)s2)[cg];
    float4 q4  = ((const float4*)q2)[cg];
    float4 mu4, is4;
    mu4.x = s4.x * inv_n; is4.x = rsqrtf(q4.x * inv_n - mu4.x * mu4.x + EPSV);
    mu4.y = s4.y * inv_n; is4.y = rsqrtf(q4.y * inv_n - mu4.y * mu4.y + EPSV);
    mu4.z = s4.z * inv_n; is4.z = rsqrtf(q4.z * inv_n - mu4.z * mu4.z + EPSV);
    mu4.w = s4.w * inv_n; is4.w = rsqrtf(q4.w * inv_n - mu4.w * mu4.w + EPSV);
    float4 sc, sf;
    sc.x = is4.x * gm4.x; sf.x = be4.x - mu4.x * sc.x;
    sc.y = is4.y * gm4.y; sf.y = be4.y - mu4.y * sc.y;
    sc.z = is4.z * gm4.z; sf.z = be4.z - mu4.z * sc.z;
    sc.w = is4.w * gm4.w; sf.w = be4.w - mu4.w * sc.w;

    float4 acc = make_float4(0.f, 0.f, 0.f, 0.f);
    for (int row = blockIdx.x * 16 + rl; row < n; row += gridDim.x * 16) {
        float4 h = ((const float4*)(g_h + (size_t)row * 64))[cg];
        acc.x += fmaxf(fmaf(h.x, sc.x, sf.x), 0.f);
        acc.y += fmaxf(fmaf(h.y, sc.y, sf.y), 0.f);
        acc.z += fmaxf(fmaf(h.z, sc.z, sf.z), 0.f);
        acc.w += fmaxf(fmaf(h.w, sc.w, sf.w), 0.f);
    }
    __shared__ float s[16][64];
    s[rl][cg * 4 + 0] = acc.x; s[rl][cg * 4 + 1] = acc.y;
    s[rl][cg * 4 + 2] = acc.z; s[rl][cg * 4 + 3] = acc.w;
    __syncthreads();
    if (threadIdx.x < 64) {
        float tsum = 0;
        #pragma unroll
        for (int r = 0; r < 16; r++) tsum += s[r][threadIdx.x];
        atomicAdd(&colsum[threadIdx.x], tsum);
    }
    __threadfence();
    __syncthreads();
    __shared__ int is_last;
    if (threadIdx.x == 0) {
        int prev = atomicAdd(done, 1);
        is_last = (prev == gridDim.x - 1);
    }
    __syncthreads();
    if (is_last) {
        __shared__ float s0[64], s1[64];
        if (threadIdx.x < 64) {
            int t = threadIdx.x;
            float v = atomicAdd(&colsum[t], 0.0f) * inv_n;   // L2-coherent read
            s0[t] = v * Wc[t * 2 + 0];
            s1[t] = v * Wc[t * 2 + 1];
        }
        __syncthreads();
        if (threadIdx.x == 0) {
            float a = 0.f, b = 0.f;
            for (int k = 0; k < 64; k++) { a += s0[k]; b += s1[k]; }
            out[0] = a + bc[0];
            out[1] = b + bc[1];
        }
    }
}

// ---------------- launch ----------------
extern "C" void kernel_launch(void* const* d_in, const int* in_sizes, int n_in,
                              void* d_out, int out_size) {
    const float* x   = (const float*)d_in[0];
    const int*   src = (const int*)d_in[1];
    const int*   dst = (const int*)d_in[2];
    const float* W1  = (const float*)d_in[3];
    const float* b1  = (const float*)d_in[4];
    const float* g1  = (const float*)d_in[5];
    const float* be1 = (const float*)d_in[6];
    const float* W2  = (const float*)d_in[7];
    const float* b2  = (const float*)d_in[8];
    const float* g2  = (const float*)d_in[9];
    const float* be2 = (const float*)d_in[10];
    const float* Wc  = (const float*)d_in[11];
    const float* bc  = (const float*)d_in[12];
    float* out = (float*)d_out;

    int n = in_sizes[0] / 64;
    int e = in_sizes[1];

    int eb = (e + 255) / 256;
    int spmm_blocks = (n + 7) / 8;
    int gemm_blocks = (n + 63) / 64;

    int* blob_d;
    cudaGetSymbolAddress((void**)&blob_d, g_blob);
    float* ds1  = (float*)(blob_d + OFF_STATS);
    float* dq1  = ds1 + 64;
    float* ds2  = ds1 + 128;
    float* dq2  = ds1 + 192;
    float* dcol = ds1 + 256;
    int*   ddone = blob_d + OFF_STATS + 320;

    // zero degrees + stats + counter in one memset node
    cudaMemsetAsync(blob_d, 0, (size_t)BLOB_INTS * sizeof(int));

    // graph preprocessing (CSR by dst) — reused by both convs
    k_deg<<<eb, 256>>>(src, dst, e);
    k_scan_p1<<<SCAN_BLOCKS, SCAN_TPB>>>(n);
    k_scan_p3<<<SCAN_BLOCKS, SCAN_TPB>>>(n);
    k_scatter<<<eb, 256>>>(src, dst, e);

    // conv 1 (bf16 gather of rs_out*x)
    k_x2bf<<<512, 256>>>(x, n * 16);
    k_spmm<0><<<spmm_blocks, 256>>>(n);
    k_gemm<<<gemm_blocks, 256>>>(W1, b1, ds1, dq1, n);

    // conv 2 (bf16 gather of rs_out*relu(bn(h1)))
    k_actbf<<<512, 256>>>(ds1, dq1, g1, be1, n);
    k_spmm<1><<<spmm_blocks, 256>>>(n);
    k_gemm<<<gemm_blocks, 256>>>(W2, b2, ds2, dq2, n);

    // fused readout + classifier
    k_colsum_final<<<512, 256>>>(ds2, dq2, g2, be2, dcol, ddone, Wc, bc, out, n);
    (void)n_in; (void)out_size;
}

// round 12
// speedup vs baseline: 1.7582x; 1.0126x over previous
#include <cuda_runtime.h>
#include <cuda_bf16.h>

// CoPEModel GCN on GB300.
// CSR-build (rank-recorded histogram -> atomic-free scatter) + bf16-gather
// pull-mode SpMM with rs_out pre-scaled into features + f32x2 GEMM with fused
// BN stats + fused colsum/readout.
// Inputs (metadata order): x, src, dst, W1, b1, g1, be1, W2, b2, g2, be2, Wc, bc
// Output: [1,2] float32.

#define NMAX 100000
#define EMAX 1600000

#define SCAN_BLOCKS 128
#define SCAN_TPB    256
#define SCAN_T      (SCAN_BLOCKS * SCAN_TPB)   // 32768 scan threads
#define SCAN_CHUNK  4                          // ceil(100000/32768)

#define EPSV 1e-5f

typedef unsigned long long ull;

// ---- zero-initialized-per-launch blob (single memset node) ----
// [0,N): deg_out  [N,2N): deg_in  [2N..): s1,q1,s2,q2,colsum,done
#define OFF_DEG_OUT 0
#define OFF_DEG_IN  NMAX
#define OFF_STATS   (2 * NMAX)
#define BLOB_INTS   (2 * NMAX + 384)
__device__ __align__(16) int g_blob[BLOB_INTS];

__device__ __align__(16) float g_rs_out[NMAX];
__device__ __align__(16) float g_rs_in[NMAX];
__device__ __align__(16) int   g_row_ptr[NMAX + 1];
__device__ __align__(16) int   g_rank[EMAX];            // intra-dst rank of each edge
__device__ __align__(16) int   g_col[EMAX];             // CSR column (src) indices
__device__ __align__(16) int   g_tpre[SCAN_T];
__device__ __align__(16) int   g_bsum[SCAN_BLOCKS];
__device__ __align__(16) __nv_bfloat162 g_xb[(size_t)NMAX * 32];  // bf16 rs_out*x
__device__ __align__(16) __nv_bfloat162 g_ab[(size_t)NMAX * 32];  // bf16 rs_out*relu(bn(h1))
__device__ __align__(16) float g_m[(size_t)NMAX * 64];  // aggregated messages
__device__ __align__(16) float g_h[(size_t)NMAX * 64];  // post-GEMM

// ---------------- f32x2 helpers ----------------
__device__ __forceinline__ void f2unpack(ull v, float& a, float& b) {
    asm("mov.b64 {%0, %1}, %2;" : "=f"(a), "=f"(b) : "l"(v));
}
__device__ __forceinline__ ull f2fma(ull a, ull b, ull c) {
    ull d; asm("fma.rn.f32x2 %0, %1, %2, %3;" : "=l"(d) : "l"(a), "l"(b), "l"(c)); return d;
}

// ---------------- graph preprocessing ----------------

// Degree histogram; the deg_in atomic RETURNS this edge's rank within its dst
// bucket, recorded coalesced — the scatter then needs no atomic at all.
__global__ void k_deg(const int* __restrict__ src, const int* __restrict__ dst, int e) {
    int i = blockIdx.x * blockDim.x + threadIdx.x;
    if (i < e) {
        g_rank[i] = atomicAdd(&g_blob[OFF_DEG_IN + dst[i]], 1);
        atomicAdd(&g_blob[OFF_DEG_OUT + src[i]], 1);
    }
}

// Phase 1: per-thread chunk sums + rsqrt degrees + block-level scan.
__global__ void k_scan_p1(int n) {
    __shared__ int sh[SCAN_TPB];
    int t = threadIdx.x;
    int g = blockIdx.x * SCAN_TPB + t;
    int beg = g * SCAN_CHUNK;
    int end = min(beg + SCAN_CHUNK, n);
    int s = 0;
    for (int i = beg; i < end; i++) {
        int di = g_blob[OFF_DEG_IN + i];
        s += di;
        g_rs_in[i]  = rsqrtf((float)max(di, 1));
        g_rs_out[i] = rsqrtf((float)max(g_blob[OFF_DEG_OUT + i], 1));
    }
    sh[t] = s;
    __syncthreads();
    for (int off = 1; off < SCAN_TPB; off <<= 1) {
        int v = (t >= off) ? sh[t - off] : 0;
        __syncthreads();
        sh[t] += v;
        __syncthreads();
    }
    g_tpre[g] = sh[t] - s;
    if (t == SCAN_TPB - 1) g_bsum[blockIdx.x] = sh[t];
}

// Phase 3 (phase 2 inlined): each block reduces its block-sum prefix, writes row_ptr.
__global__ void k_scan_p3(int n) {
    __shared__ int sb[SCAN_BLOCKS];
    int t = threadIdx.x;
    if (t < SCAN_BLOCKS) sb[t] = (t < blockIdx.x) ? g_bsum[t] : 0;
    __syncthreads();
    for (int off = SCAN_BLOCKS / 2; off >= 1; off >>= 1) {
        if (t < off) sb[t] += sb[t + off];
        __syncthreads();
    }
    int bpre = sb[0];
    int g = blockIdx.x * SCAN_TPB + t;
    int beg = g * SCAN_CHUNK;
    int end = min(beg + SCAN_CHUNK, n);
    int base = bpre + g_tpre[g];
    for (int i = beg; i < end; i++) {
        g_row_ptr[i] = base;
        base += g_blob[OFF_DEG_IN + i];
    }
    if (end == n && beg < n) g_row_ptr[n] = base;
}

// Atomic-free scatter: position = row_ptr[dst] + recorded rank.
__global__ void k_scatter(const int* __restrict__ src, const int* __restrict__ dst, int e) {
    int i = blockIdx.x * blockDim.x + threadIdx.x;
    if (i < e) {
        int p = g_row_ptr[dst[i]] + g_rank[i];
        g_col[p] = src[i];
    }
}

// ---------------- bf16 conversion passes (rs_out pre-scaled) ----------------

// rs_out[row]*x (fp32) -> g_xb (bf16). n*16 float4 elements; row = i>>4.
__global__ void k_x2bf(const float* __restrict__ x, int n16) {
    int i = blockIdx.x * blockDim.x + threadIdx.x;
    int stride = gridDim.x * blockDim.x;
    const float4* x4 = (const float4*)x;
    uint2* ob = (uint2*)g_xb;
    for (; i < n16; i += stride) {
        float ro = g_rs_out[i >> 4];
        float4 f = x4[i];
        __nv_bfloat162 lo = __floats2bfloat162_rn(f.x * ro, f.y * ro);
        __nv_bfloat162 hi = __floats2bfloat162_rn(f.z * ro, f.w * ro);
        uint2 v;
        v.x = *(unsigned*)&lo;
        v.y = *(unsigned*)&hi;
        ob[i] = v;
    }
}

// rs_out[row]*relu(bn(g_h)) -> g_ab (bf16), conv-1 epilogue, BN inline.
// grid*block multiple of 16 so each thread's channel group is fixed.
__global__ void k_actbf(const float* __restrict__ s1, const float* __restrict__ q1,
                        const float* __restrict__ gma, const float* __restrict__ bet,
                        int n) {
    int i = blockIdx.x * blockDim.x + threadIdx.x;
    int stride = gridDim.x * blockDim.x;
    int cg = i & 15;
    float inv_n = 1.f / (float)n;
    float sc[4], sf[4];
    #pragma unroll
    for (int k = 0; k < 4; k++) {
        int c = cg * 4 + k;
        float mu = s1[c] * inv_n;
        float is = rsqrtf(q1[c] * inv_n - mu * mu + EPSV);
        sc[k] = is * gma[c];
        sf[k] = bet[c] - mu * sc[k];
    }
    const float4* h4 = (const float4*)g_h;
    uint2* ob = (uint2*)g_ab;
    int n16 = n * 16;
    for (; i < n16; i += stride) {
        float ro = g_rs_out[i >> 4];
        float4 h = h4[i];
        float y0 = fmaxf(fmaf(h.x, sc[0], sf[0]), 0.f) * ro;
        float y1 = fmaxf(fmaf(h.y, sc[1], sf[1]), 0.f) * ro;
        float y2 = fmaxf(fmaf(h.z, sc[2], sf[2]), 0.f) * ro;
        float y3 = fmaxf(fmaf(h.w, sc[3], sf[3]), 0.f) * ro;
        __nv_bfloat162 lo = __floats2bfloat162_rn(y0, y1);
        __nv_bfloat162 hi = __floats2bfloat162_rn(y2, y3);
        uint2 v;
        v.x = *(unsigned*)&lo;
        v.y = *(unsigned*)&hi;
        ob[i] = v;
    }
}

// ---------------- pull-mode SpMM (bf16 gather, fp32 accumulate) ----------------
// m[v] = rs_in[v] * sum_{u in N_in(v)} in[u]   (rs_out already folded into in)
// WHICH=0 reads g_xb (conv 1), WHICH=1 reads g_ab (conv 2). Scratch arrays
// referenced in DEVICE code only. One warp per node; lane owns 2 channels.
// 8-wide full batches + scalar remainder.
template <int WHICH>
__global__ void k_spmm(int n) {
    const __nv_bfloat162* __restrict__ in = WHICH ? g_ab : g_xb;
    int warp = (blockIdx.x * blockDim.x + threadIdx.x) >> 5;
    int lane = threadIdx.x & 31;
    if (warp >= n) return;

    int beg = g_row_ptr[warp], end = g_row_ptr[warp + 1];
    float accx = 0.f, accy = 0.f;
    int j = beg;
    for (; j + 8 <= end; j += 8) {
        int u[8];
        #pragma unroll
        for (int i = 0; i < 8; i++) u[i] = __ldg(&g_col[j + i]);
        float2 v[8];
        #pragma unroll
        for (int i = 0; i < 8; i++) {
            __nv_bfloat162 b = __ldg(&in[(size_t)u[i] * 32 + lane]);
            v[i] = __bfloat1622float2(b);
        }
        #pragma unroll
        for (int i = 0; i < 8; i++) {
            accx += v[i].x;
            accy += v[i].y;
        }
    }
    for (; j < end; j++) {
        int u = __ldg(&g_col[j]);
        __nv_bfloat162 b = __ldg(&in[(size_t)u * 32 + lane]);
        float2 v = __bfloat1622float2(b);
        accx += v.x;
        accy += v.y;
    }
    float ri = g_rs_in[warp];
    *(float2*)(g_m + (size_t)warp * 64 + lane * 2) = make_float2(accx * ri, accy * ri);
}

// ---------------- f32x2 GEMM (g_m @ W + b -> g_h) with fused BN statistics ----------------
__global__ void k_gemm(const float* __restrict__ W, const float* __restrict__ bias,
                       float* __restrict__ sumbuf, float* __restrict__ sqbuf, int n) {
    __shared__ float Wt[64][66];
    __shared__ float s_sum[16][64];
    __shared__ float s_sq[16][64];
    int t = threadIdx.x;
    for (int idx = t; idx < 4096; idx += 256) {
        int k = idx >> 6, jj = idx & 63;
        Wt[jj][k] = W[idx];
    }
    __syncthreads();

    int jg = t & 15, rslot = t >> 4;
    int row0 = blockIdx.x * 64 + rslot * 4;

    const ull* m0 = (const ull*)(g_m + (size_t)(row0 + 0) * 64);
    const ull* m1 = (const ull*)(g_m + (size_t)(row0 + 1) * 64);
    const ull* m2p = (const ull*)(g_m + (size_t)(row0 + 2) * 64);
    const ull* m3 = (const ull*)(g_m + (size_t)(row0 + 3) * 64);
    bool val0 = row0 + 0 < n, val1 = row0 + 1 < n, val2 = row0 + 2 < n, val3 = row0 + 3 < n;

    ull acc[4][4];
    #pragma unroll
    for (int r = 0; r < 4; r++)
        #pragma unroll
        for (int i = 0; i < 4; i++) acc[r][i] = 0ULL;

    #pragma unroll 4
    for (int k2 = 0; k2 < 32; k2++) {
        ull a0 = val0 ? m0[k2] : 0ULL;
        ull a1 = val1 ? m1[k2] : 0ULL;
        ull a2 = val2 ? m2p[k2] : 0ULL;
        ull a3 = val3 ? m3[k2] : 0ULL;
        #pragma unroll
        for (int i = 0; i < 4; i++) {
            ull w2 = *(const ull*)&Wt[jg + 16 * i][k2 * 2];
            acc[0][i] = f2fma(a0, w2, acc[0][i]);
            acc[1][i] = f2fma(a1, w2, acc[1][i]);
            acc[2][i] = f2fma(a2, w2, acc[2][i]);
            acc[3][i] = f2fma(a3, w2, acc[3][i]);
        }
    }

    float ls[4] = {0, 0, 0, 0}, lq[4] = {0, 0, 0, 0};
    bool vr[4] = {val0, val1, val2, val3};
    #pragma unroll
    for (int r = 0; r < 4; r++) {
        if (vr[r]) {
            int row = row0 + r;
            #pragma unroll
            for (int i = 0; i < 4; i++) {
                int c = jg + 16 * i;
                float lo, hi;
                f2unpack(acc[r][i], lo, hi);
                float v = lo + hi + bias[c];
                g_h[(size_t)row * 64 + c] = v;
                ls[i] += v;
                lq[i] += v * v;
            }
        }
    }
    #pragma unroll
    for (int i = 0; i < 4; i++) {
        int c = jg + 16 * i;
        s_sum[rslot][c] = ls[i];
        s_sq[rslot][c]  = lq[i];
    }
    __syncthreads();
    if (t < 64) {
        float a = 0, q = 0;
        #pragma unroll
        for (int r = 0; r < 16; r++) { a += s_sum[r][t]; q += s_sq[r][t]; }
        atomicAdd(&sumbuf[t], a);
        atomicAdd(&sqbuf[t], q);
    }
}

// ---------------- fused conv-2 readout + classifier ----------------
__global__ void k_colsum_final(const float* __restrict__ s2, const float* __restrict__ q2,
                               const float* __restrict__ gma, const float* __restrict__ bet,
                               float* __restrict__ colsum, int* __restrict__ done,
                               const float* __restrict__ Wc, const float* __restrict__ bc,
                               float* __restrict__ out, int n) {
    int cg = threadIdx.x & 15;
    int rl = threadIdx.x >> 4;
    float inv_n = 1.f / (float)n;
    float4 gm4 = ((const float4*)gma)[cg];
    float4 be4 = ((const float4*)bet)[cg];
    float4 s4  = ((const float4*)s2)[cg];
    float4 q4  = ((const float4*)q2)[cg];
    float4 mu4, is4;
    mu4.x = s4.x * inv_n; is4.x = rsqrtf(q4.x * inv_n - mu4.x * mu4.x + EPSV);
    mu4.y = s4.y * inv_n; is4.y = rsqrtf(q4.y * inv_n - mu4.y * mu4.y + EPSV);
    mu4.z = s4.z * inv_n; is4.z = rsqrtf(q4.z * inv_n - mu4.z * mu4.z + EPSV);
    mu4.w = s4.w * inv_n; is4.w = rsqrtf(q4.w * inv_n - mu4.w * mu4.w + EPSV);
    float4 sc, sf;
    sc.x = is4.x * gm4.x; sf.x = be4.x - mu4.x * sc.x;
    sc.y = is4.y * gm4.y; sf.y = be4.y - mu4.y * sc.y;
    sc.z = is4.z * gm4.z; sf.z = be4.z - mu4.z * sc.z;
    sc.w = is4.w * gm4.w; sf.w = be4.w - mu4.w * sc.w;

    float4 acc = make_float4(0.f, 0.f, 0.f, 0.f);
    for (int row = blockIdx.x * 16 + rl; row < n; row += gridDim.x * 16) {
        float4 h = ((const float4*)(g_h + (size_t)row * 64))[cg];
        acc.x += fmaxf(fmaf(h.x, sc.x, sf.x), 0.f);
        acc.y += fmaxf(fmaf(h.y, sc.y, sf.y), 0.f);
        acc.z += fmaxf(fmaf(h.z, sc.z, sf.z), 0.f);
        acc.w += fmaxf(fmaf(h.w, sc.w, sf.w), 0.f);
    }
    __shared__ float s[16][64];
    s[rl][cg * 4 + 0] = acc.x; s[rl][cg * 4 + 1] = acc.y;
    s[rl][cg * 4 + 2] = acc.z; s[rl][cg * 4 + 3] = acc.w;
    __syncthreads();
    if (threadIdx.x < 64) {
        float tsum = 0;
        #pragma unroll
        for (int r = 0; r < 16; r++) tsum += s[r][threadIdx.x];
        atomicAdd(&colsum[threadIdx.x], tsum);
    }
    __threadfence();
    __syncthreads();
    __shared__ int is_last;
    if (threadIdx.x == 0) {
        int prev = atomicAdd(done, 1);
        is_last = (prev == gridDim.x - 1);
    }
    __syncthreads();
    if (is_last) {
        __shared__ float s0[64], s1[64];
        if (threadIdx.x < 64) {
            int t = threadIdx.x;
            float v = atomicAdd(&colsum[t], 0.0f) * inv_n;   // L2-coherent read
            s0[t] = v * Wc[t * 2 + 0];
            s1[t] = v * Wc[t * 2 + 1];
        }
        __syncthreads();
        if (threadIdx.x == 0) {
            float a = 0.f, b = 0.f;
            for (int k = 0; k < 64; k++) { a += s0[k]; b += s1[k]; }
            out[0] = a + bc[0];
            out[1] = b + bc[1];
        }
    }
}

// ---------------- launch ----------------
extern "C" void kernel_launch(void* const* d_in, const int* in_sizes, int n_in,
                              void* d_out, int out_size) {
    const float* x   = (const float*)d_in[0];
    const int*   src = (const int*)d_in[1];
    const int*   dst = (const int*)d_in[2];
    const float* W1  = (const float*)d_in[3];
    const float* b1  = (const float*)d_in[4];
    const float* g1  = (const float*)d_in[5];
    const float* be1 = (const float*)d_in[6];
    const float* W2  = (const float*)d_in[7];
    const float* b2  = (const float*)d_in[8];
    const float* g2  = (const float*)d_in[9];
    const float* be2 = (const float*)d_in[10];
    const float* Wc  = (const float*)d_in[11];
    const float* bc  = (const float*)d_in[12];
    float* out = (float*)d_out;

    int n = in_sizes[0] / 64;
    int e = in_sizes[1];

    int eb = (e + 255) / 256;
    int spmm_blocks = (n + 7) / 8;
    int gemm_blocks = (n + 63) / 64;

    int* blob_d;
    cudaGetSymbolAddress((void**)&blob_d, g_blob);
    float* ds1  = (float*)(blob_d + OFF_STATS);
    float* dq1  = ds1 + 64;
    float* ds2  = ds1 + 128;
    float* dq2  = ds1 + 192;
    float* dcol = ds1 + 256;
    int*   ddone = blob_d + OFF_STATS + 320;

    // zero degrees + stats + counter in one memset node
    cudaMemsetAsync(blob_d, 0, (size_t)BLOB_INTS * sizeof(int));

    // graph preprocessing (CSR by dst, rank-based) — reused by both convs
    k_deg<<<eb, 256>>>(src, dst, e);
    k_scan_p1<<<SCAN_BLOCKS, SCAN_TPB>>>(n);
    k_scan_p3<<<SCAN_BLOCKS, SCAN_TPB>>>(n);
    k_scatter<<<eb, 256>>>(src, dst, e);

    // conv 1 (bf16 gather of rs_out*x)
    k_x2bf<<<512, 256>>>(x, n * 16);
    k_spmm<0><<<spmm_blocks, 256>>>(n);
    k_gemm<<<gemm_blocks, 256>>>(W1, b1, ds1, dq1, n);

    // conv 2 (bf16 gather of rs_out*relu(bn(h1)))
    k_actbf<<<512, 256>>>(ds1, dq1, g1, be1, n);
    k_spmm<1><<<spmm_blocks, 256>>>(n);
    k_gemm<<<gemm_blocks, 256>>>(W2, b2, ds2, dq2, n);

    // fused readout + classifier
    k_colsum_final<<<512, 256>>>(ds2, dq2, g2, be2, dcol, ddone, Wc, bc, out, n);
    (void)n_in; (void)out_size;
}